// round 10
// baseline (speedup 1.0000x reference)
#include <cuda_runtime.h>
#include <cuda_fp16.h>
#include <stdint.h>
#include <math.h>

#define MROWS 4096

// ---------------- scratch (fp16 operands) ----------------
__device__ __half g_ln  [(size_t)MROWS * 1024];
__device__ __half g_ctx [(size_t)MROWS * 1024];
__device__ __half g_wqkv[(size_t)1024 * 3072];
__device__ __half g_wout[(size_t)1024 * 1024];
__device__ __half g_w1  [(size_t)1024 * 4096];
__device__ __half g_w2  [(size_t)4096 * 1024];
__device__ __half g_ffn1[(size_t)MROWS * 4096];
__device__ __half g_qkvh[(size_t)MROWS * 3072];
__device__ float  g_x1  [(size_t)MROWS * 1024];

__device__ __forceinline__ const __half* bufh(int c)
{
    switch (c) {
        case 1: return g_ln;
        case 2: return g_ctx;
        case 3: return g_wqkv;
        case 4: return g_wout;
        case 5: return g_w1;
        case 6: return g_w2;
        case 7: return g_ffn1;
        default: return g_qkvh;
    }
}
__device__ __forceinline__ float* buff(int c, const float* p)
{
    switch (c) {
        case 2: return g_x1;
        default: return (float*)p;
    }
}

// ---------------- PTX helpers (baseline PTX; safe on plain sm_103) ----------
__device__ __forceinline__ uint32_t smem_u32(const void* p)
{
    uint32_t a;
    asm("{ .reg .u64 t; cvta.to.shared.u64 t, %1; cvt.u32.u64 %0, t; }" : "=r"(a) : "l"(p));
    return a;
}
__device__ __forceinline__ void ldm_x4(uint32_t* r, uint32_t a)
{
    asm volatile("ldmatrix.sync.aligned.m8n8.x4.shared.b16 {%0,%1,%2,%3}, [%4];"
        : "=r"(r[0]), "=r"(r[1]), "=r"(r[2]), "=r"(r[3]) : "r"(a));
}
__device__ __forceinline__ void ldm_x4_t(uint32_t* r, uint32_t a)
{
    asm volatile("ldmatrix.sync.aligned.m8n8.x4.trans.shared.b16 {%0,%1,%2,%3}, [%4];"
        : "=r"(r[0]), "=r"(r[1]), "=r"(r[2]), "=r"(r[3]) : "r"(a));
}
__device__ __forceinline__ void mma_f16(float* c, const uint32_t* a, const uint32_t* b)
{
    asm volatile("mma.sync.aligned.m16n8k16.row.col.f32.f16.f16.f32 "
        "{%0,%1,%2,%3}, {%4,%5,%6,%7}, {%8,%9}, {%0,%1,%2,%3};"
        : "+f"(c[0]), "+f"(c[1]), "+f"(c[2]), "+f"(c[3])
        : "r"(a[0]), "r"(a[1]), "r"(a[2]), "r"(a[3]), "r"(b[0]), "r"(b[1]));
}
__device__ __forceinline__ void cpa16(uint32_t s, const void* g)
{
    asm volatile("cp.async.cg.shared.global [%0], [%1], 16;" :: "r"(s), "l"(g));
}
#define CPA_COMMIT() asm volatile("cp.async.commit_group;" ::: "memory")
#define CPA_WAIT(n)  asm volatile("cp.async.wait_group %0;" :: "n"(n) : "memory")

// ---------------- merged weight casts: f32 -> f16 ----------------
__global__ __launch_bounds__(256) void cast_ab_kernel(const float* __restrict__ wqkv,
                                                      const float* __restrict__ wout)
{
    const int bid = blockIdx.x;
    const float* src = (bid < 3072) ? wqkv : wout;
    __half* dst = (bid < 3072) ? g_wqkv : g_wout;
    const size_t i = (size_t)(bid < 3072 ? bid : bid - 3072) * 256 + threadIdx.x;
    const float4 v = reinterpret_cast<const float4*>(src)[i];
    *(__half2*)&dst[i * 4]     = __floats2half2_rn(v.x, v.y);
    *(__half2*)&dst[i * 4 + 2] = __floats2half2_rn(v.z, v.w);
}
__global__ __launch_bounds__(256) void cast_cd_kernel(const float* __restrict__ w1,
                                                      const float* __restrict__ w2)
{
    const int bid = blockIdx.x;
    const float* src = (bid < 4096) ? w1 : w2;
    __half* dst = (bid < 4096) ? g_w1 : g_w2;
    const size_t i = (size_t)(bid < 4096 ? bid : bid - 4096) * 256 + threadIdx.x;
    const float4 v = reinterpret_cast<const float4*>(src)[i];
    *(__half2*)&dst[i * 4]     = __floats2half2_rn(v.x, v.y);
    *(__half2*)&dst[i * 4 + 2] = __floats2half2_rn(v.z, v.w);
}

// ---------------- LayerNorm -> fp16 [row, 1024] ----------------
__global__ __launch_bounds__(256) void ln_h_kernel(const float* __restrict__ xp, int xc,
                                                   const float* __restrict__ gam,
                                                   const float* __restrict__ bet)
{
    const float* x = buff(xc, xp);
    __shared__ float sh[8];
    __shared__ float stat[2];
    const int row = blockIdx.x, t = threadIdx.x;

    const float4 v = reinterpret_cast<const float4*>(x)[(size_t)row * 256 + t];
    float s = v.x + v.y + v.z + v.w;
    #pragma unroll
    for (int o = 16; o; o >>= 1) s += __shfl_xor_sync(0xffffffffu, s, o);
    if ((t & 31) == 0) sh[t >> 5] = s;
    __syncthreads();
    if (t < 32) {
        float u = (t < 8) ? sh[t] : 0.f;
        #pragma unroll
        for (int o = 4; o; o >>= 1) u += __shfl_xor_sync(0xffffffffu, u, o);
        if (t == 0) stat[0] = u * (1.f / 1024.f);
    }
    __syncthreads();
    const float mu = stat[0];
    const float a = v.x - mu, b = v.y - mu, c = v.z - mu, d = v.w - mu;
    float s2 = a * a + b * b + c * c + d * d;
    #pragma unroll
    for (int o = 16; o; o >>= 1) s2 += __shfl_xor_sync(0xffffffffu, s2, o);
    if ((t & 31) == 0) sh[t >> 5] = s2;
    __syncthreads();
    if (t < 32) {
        float u = (t < 8) ? sh[t] : 0.f;
        #pragma unroll
        for (int o = 4; o; o >>= 1) u += __shfl_xor_sync(0xffffffffu, u, o);
        if (t == 0) stat[1] = rsqrtf(u * (1.f / 1024.f) + 1e-5f);
    }
    __syncthreads();
    const float inv = stat[1];
    const float4 gv = reinterpret_cast<const float4*>(gam)[t];
    const float4 bv = reinterpret_cast<const float4*>(bet)[t];
    const float o0 = a * inv * gv.x + bv.x, o1 = b * inv * gv.y + bv.y;
    const float o2 = c * inv * gv.z + bv.z, o3 = d * inv * gv.w + bv.w;
    const size_t base = (size_t)row * 1024 + t * 4;
    *(__half2*)&g_ln[base]     = __floats2half2_rn(o0, o1);
    *(__half2*)&g_ln[base + 2] = __floats2half2_rn(o2, o3);
}

// ---------------- HMMA fp16 GEMM, BK=64 double-buffered (64KB dynamic) -------
// CTA 128x128, 256 thr, 8 warps (4m x 2n). Stage: A[128x64] fp16 (16KB,
// chunk swz c^(r&7)) + B[64x128] (16KB, c^(k&7)). 2 stages, depth-1 prefetch.
#define GEMM_DSM (2 * 32768)

template<bool RELU, bool RESID, bool HALFOUT>
__global__ __launch_bounds__(256) void gemm_mma(
    int N, int KTOT, int Ac, int Bc,
    const float* __restrict__ bias,
    const float* resp, int resc,
    float* Cp, int Cc)
{
    const __half* A  = bufh(Ac);
    const __half* Bw = bufh(Bc);
    const float* res = buff(resc, resp);
    float* C = HALFOUT ? nullptr : buff(Cc, Cp);
    __half* Ch = HALFOUT ? (__half*)bufh(Cc) : nullptr;

    extern __shared__ __align__(16) char dsm[];

    const int tid = threadIdx.x;
    const int wid = tid >> 5, lane = tid & 31;
    const int wm = wid & 3, wn = wid >> 2;
    const int brow = blockIdx.y, bcol = blockIdx.x;

    const __half* Ablk = A + (size_t)(brow * 128) * KTOT;
    const __half* Bblk = Bw + bcol * 128;

    const uint32_t smB = smem_u32(dsm);

    // cp.async coords: A row ar (0..127), 4 chunks; B k-row bkr (0..63), 4 chunks
    const int ar = tid >> 1, ac0 = (tid & 1) * 4;
    const int bkr = tid >> 2, bc0 = (tid & 3) * 4;
    uint32_t aso[4], bso[4];
    #pragma unroll
    for (int j = 0; j < 4; j++) {
        aso[j] = (uint32_t)(ar * 128 + (((ac0 + j) ^ (ar & 7)) << 4));
        bso[j] = (uint32_t)(16384 + bkr * 256 + (((bc0 + j) ^ (bkr & 7)) << 4));
    }

    // ldmatrix per-lane constants
    const int lr = lane & 15, lc = lane >> 4;
    const int arow[2] = { wm * 32 + lr, wm * 32 + 16 + lr };
    const uint32_t aswz[2] = { (uint32_t)(arow[0] & 7), (uint32_t)(arow[1] & 7) };
    const uint32_t bswzk = (uint32_t)(lr & 7);

    float acc[2][8][4];
    #pragma unroll
    for (int mt = 0; mt < 2; mt++)
        #pragma unroll
        for (int nt = 0; nt < 8; nt++)
            #pragma unroll
            for (int q = 0; q < 4; q++) acc[mt][nt][q] = 0.f;

    const int NS = KTOT >> 6;

    auto issue = [&](int ss) {
        const int kg = ss * 64;
        const uint32_t st = smB + (uint32_t)((ss & 1) * 32768);
        #pragma unroll
        for (int j = 0; j < 4; j++)
            cpa16(st + aso[j], Ablk + (size_t)ar * KTOT + kg + (ac0 + j) * 8);
        #pragma unroll
        for (int j = 0; j < 4; j++)
            cpa16(st + bso[j], Bblk + (size_t)(kg + bkr) * N + (bc0 + j) * 8);
        CPA_COMMIT();
    };

    issue(0);

    #pragma unroll 1
    for (int s = 0; s < NS; s++) {
        CPA_WAIT(0);
        __syncthreads();
        if (s + 1 < NS) issue(s + 1);

        const uint32_t aB = smB + (uint32_t)((s & 1) * 32768);
        const uint32_t bB = aB + 16384;
        #pragma unroll
        for (int ks = 0; ks < 4; ks++) {
            uint32_t af[2][4], bf[4][4];
            #pragma unroll
            for (int mt = 0; mt < 2; mt++) {
                const uint32_t chunk = ((uint32_t)(ks * 2 + lc)) ^ aswz[mt];
                ldm_x4(af[mt], aB + (uint32_t)(arow[mt] * 128) + (chunk << 4));
            }
            const uint32_t kk = (uint32_t)(ks * 16 + lr);
            #pragma unroll
            for (int n16 = 0; n16 < 4; n16++) {
                const uint32_t cn = ((uint32_t)(wn * 8 + n16 * 2 + lc)) ^ bswzk;
                ldm_x4_t(bf[n16], bB + kk * 256 + (cn << 4));
            }
            #pragma unroll
            for (int mt = 0; mt < 2; mt++)
                #pragma unroll
                for (int nt = 0; nt < 8; nt++)
                    mma_f16(acc[mt][nt], af[mt], &bf[nt >> 1][(nt & 1) * 2]);
        }
    }

    const int rbase = brow * 128 + wm * 32 + (lane >> 2);
    const int cbase = bcol * 128 + wn * 64 + (lane & 3) * 2;
    #pragma unroll
    for (int mt = 0; mt < 2; mt++) {
        #pragma unroll
        for (int nt = 0; nt < 8; nt++) {
            const int c = cbase + nt * 8;
            const float2 bv = *(const float2*)(bias + c);
            #pragma unroll
            for (int hrow = 0; hrow < 2; hrow++) {
                const int r = rbase + mt * 16 + hrow * 8;
                float v0 = acc[mt][nt][hrow * 2]     + bv.x;
                float v1 = acc[mt][nt][hrow * 2 + 1] + bv.y;
                if (HALFOUT) {
                    if (RELU) { v0 = fmaxf(v0, 0.f); v1 = fmaxf(v1, 0.f); }
                    *(__half2*)&Ch[(size_t)r * N + c] = __floats2half2_rn(v0, v1);
                } else {
                    const size_t off = (size_t)r * N + c;
                    if (RESID) {
                        const float2 rv = *(const float2*)(res + off);
                        v0 += rv.x; v1 += rv.y;
                    }
                    float2 ov; ov.x = v0; ov.y = v1;
                    *(float2*)(C + off) = ov;
                }
            }
        }
    }
}

// ---------------- HMMA windowed flash attention -> g_ctx (fp16) --------------
__global__ __launch_bounds__(256) void attn_kernel(const float* __restrict__ res_pos)
{
    __shared__ __align__(16) __half Qs[128 * 64];
    __shared__ __align__(16) __half Ks[64 * 64];
    __shared__ __align__(16) __half Vs[64 * 64];
    __shared__ float rp[512];

    const __half* qkv = g_qkvh;
    const int bx = blockIdx.x, h = blockIdx.y, bb = blockIdx.z;
    const int q0 = bx * 128;
    const int tid = threadIdx.x, wid = tid >> 5, lane = tid & 31;
    const int lr = lane & 15, lc = lane >> 4;
    const int r0 = lane >> 2;

    const uint32_t qsB = smem_u32(Qs);
    const uint32_t ksB = smem_u32(Ks);
    const uint32_t vsB = smem_u32(Vs);

    for (int i = tid; i < 512; i += 256) rp[i] = res_pos[h * 512 + i];

    #pragma unroll
    for (int i = 0; i < 4; i++) {
        const int idx = i * 256 + tid;
        const int r = idx >> 3, c = idx & 7;
        *(uint4*)((char*)Qs + r * 128 + (((uint32_t)c ^ (r & 7)) << 4)) =
            *(const uint4*)(qkv + (size_t)(bb * 2048 + q0 + r) * 3072 + h * 64 + c * 8);
    }
    __syncthreads();

    uint32_t qf[4][4];
    #pragma unroll
    for (int ks = 0; ks < 4; ks++) {
        const int row = wid * 16 + lr;
        const uint32_t chunk = ((uint32_t)(2 * ks + lc)) ^ (row & 7);
        ldm_x4(qf[ks], qsB + (uint32_t)(row * 128) + (chunk << 4));
    }

    float m0 = -1e30f, m8 = -1e30f, l0 = 0.f, l8 = 0.f;
    float of[8][4];
    #pragma unroll
    for (int nt = 0; nt < 8; nt++)
        #pragma unroll
        for (int q = 0; q < 4; q++) of[nt][q] = 0.f;

    const int ktlo = (q0 >= 511) ? ((q0 - 511) >> 6) : 0;
    const int kthi = (q0 + 127) >> 6;

    for (int kt = ktlo; kt <= kthi; kt++) {
        __syncthreads();
        #pragma unroll
        for (int i = 0; i < 4; i++) {
            const int idx = i * 256 + tid;
            const int arr = idx >> 9, rem = idx & 511;
            const int r = rem >> 3, c = rem & 7;
            const uint4 v = *(const uint4*)(qkv + (size_t)(bb * 2048 + kt * 64 + r) * 3072
                                            + 1024 + arr * 1024 + h * 64 + c * 8);
            char* dst = arr ? (char*)Vs : (char*)Ks;
            *(uint4*)(dst + r * 128 + (((uint32_t)c ^ (r & 7)) << 4)) = v;
        }
        __syncthreads();

        float sc[8][4];
        #pragma unroll
        for (int nt = 0; nt < 8; nt++)
            #pragma unroll
            for (int q = 0; q < 4; q++) sc[nt][q] = 0.f;
        #pragma unroll
        for (int cd = 0; cd < 4; cd++) {
            uint32_t kb[4][4];
            #pragma unroll
            for (int g = 0; g < 4; g++) {
                const int kr = g * 16 + lr;
                const uint32_t chunk = ((uint32_t)(2 * cd + lc)) ^ (kr & 7);
                ldm_x4(kb[g], ksB + (uint32_t)(kr * 128) + (chunk << 4));
            }
            #pragma unroll
            for (int nt = 0; nt < 8; nt++) {
                uint32_t bp[2];
                const int g = nt >> 1;
                if (nt & 1) { bp[0] = kb[g][1]; bp[1] = kb[g][3]; }
                else        { bp[0] = kb[g][0]; bp[1] = kb[g][2]; }
                mma_f16(sc[nt], qf[cd], bp);
            }
        }

        const int qr = q0 + wid * 16 + r0;
        #pragma unroll
        for (int nt = 0; nt < 8; nt++) {
            const int key0 = kt * 64 + nt * 8 + (lane & 3) * 2;
            #pragma unroll
            for (int j = 0; j < 2; j++) {
                const int dd  = qr - (key0 + j);
                const int dd8 = dd + 8;
                sc[nt][j]     = (dd  >= 0 && dd  < 512) ? sc[nt][j]     * 0.125f + rp[dd]  : -1e30f;
                sc[nt][2 + j] = (dd8 >= 0 && dd8 < 512) ? sc[nt][2 + j] * 0.125f + rp[dd8] : -1e30f;
            }
        }

        float t0 = -1e30f, t8 = -1e30f;
        #pragma unroll
        for (int nt = 0; nt < 8; nt++) {
            t0 = fmaxf(t0, fmaxf(sc[nt][0], sc[nt][1]));
            t8 = fmaxf(t8, fmaxf(sc[nt][2], sc[nt][3]));
        }
        #pragma unroll
        for (int o = 1; o <= 2; o <<= 1) {
            t0 = fmaxf(t0, __shfl_xor_sync(0xffffffffu, t0, o));
            t8 = fmaxf(t8, __shfl_xor_sync(0xffffffffu, t8, o));
        }
        const float mn0 = fmaxf(m0, t0), mn8 = fmaxf(m8, t8);
        const float al0 = __expf(m0 - mn0), al8 = __expf(m8 - mn8);
        m0 = mn0; m8 = mn8;
        float rs0 = 0.f, rs8 = 0.f;
        #pragma unroll
        for (int nt = 0; nt < 8; nt++) {
            sc[nt][0] = __expf(sc[nt][0] - mn0); rs0 += sc[nt][0];
            sc[nt][1] = __expf(sc[nt][1] - mn0); rs0 += sc[nt][1];
            sc[nt][2] = __expf(sc[nt][2] - mn8); rs8 += sc[nt][2];
            sc[nt][3] = __expf(sc[nt][3] - mn8); rs8 += sc[nt][3];
        }
        #pragma unroll
        for (int o = 1; o <= 2; o <<= 1) {
            rs0 += __shfl_xor_sync(0xffffffffu, rs0, o);
            rs8 += __shfl_xor_sync(0xffffffffu, rs8, o);
        }
        l0 = l0 * al0 + rs0;
        l8 = l8 * al8 + rs8;
        #pragma unroll
        for (int nt = 0; nt < 8; nt++) {
            of[nt][0] *= al0; of[nt][1] *= al0;
            of[nt][2] *= al8; of[nt][3] *= al8;
        }

        #pragma unroll
        for (int ks = 0; ks < 4; ks++) {
            uint32_t ap[4];
            __half2 h0 = __floats2half2_rn(sc[2 * ks][0],     sc[2 * ks][1]);
            __half2 h1 = __floats2half2_rn(sc[2 * ks][2],     sc[2 * ks][3]);
            __half2 h2 = __floats2half2_rn(sc[2 * ks + 1][0], sc[2 * ks + 1][1]);
            __half2 h3 = __floats2half2_rn(sc[2 * ks + 1][2], sc[2 * ks + 1][3]);
            ap[0] = *(uint32_t*)&h0; ap[1] = *(uint32_t*)&h1;
            ap[2] = *(uint32_t*)&h2; ap[3] = *(uint32_t*)&h3;
            uint32_t vb[4][4];
            const int kk = ks * 16 + lr;
            #pragma unroll
            for (int nv = 0; nv < 4; nv++) {
                const uint32_t cn = ((uint32_t)(2 * nv + lc)) ^ (kk & 7);
                ldm_x4_t(vb[nv], vsB + (uint32_t)(kk * 128) + (cn << 4));
            }
            #pragma unroll
            for (int nt = 0; nt < 8; nt++)
                mma_f16(of[nt], ap, &vb[nt >> 1][(nt & 1) * 2]);
        }
    }

    const float rl0 = 1.f / l0, rl8 = 1.f / l8;
    const int rowA = bb * 2048 + q0 + wid * 16 + r0;
    #pragma unroll
    for (int nt = 0; nt < 8; nt++) {
        const int c = h * 64 + nt * 8 + (lane & 3) * 2;
        *(__half2*)&g_ctx[(size_t)rowA * 1024 + c] =
            __floats2half2_rn(of[nt][0] * rl0, of[nt][1] * rl0);
        *(__half2*)&g_ctx[(size_t)(rowA + 8) * 1024 + c] =
            __floats2half2_rn(of[nt][2] * rl8, of[nt][3] * rl8);
    }
}

// ---------------- launch ----------------
extern "C" void kernel_launch(void* const* d_in, const int* in_sizes, int n_in,
                              void* d_out, int out_size)
{
    (void)in_sizes; (void)n_in; (void)out_size;
    const float* x      = (const float*)d_in[0];
    const float* respos = (const float*)d_in[1];
    const float* w_qkv  = (const float*)d_in[2];
    const float* b_qkv  = (const float*)d_in[3];
    const float* w_out  = (const float*)d_in[4];
    const float* b_out  = (const float*)d_in[5];
    const float* w1     = (const float*)d_in[6];
    const float* b1     = (const float*)d_in[7];
    const float* w2     = (const float*)d_in[8];
    const float* b2     = (const float*)d_in[9];
    const float* ln1_g  = (const float*)d_in[10];
    const float* ln1_b  = (const float*)d_in[11];
    const float* ln2_g  = (const float*)d_in[12];
    const float* ln2_b  = (const float*)d_in[13];
    float* out = (float*)d_out;

    cudaFuncSetAttribute(gemm_mma<false, false, true >, cudaFuncAttributeMaxDynamicSharedMemorySize, GEMM_DSM);
    cudaFuncSetAttribute(gemm_mma<false, true,  false>, cudaFuncAttributeMaxDynamicSharedMemorySize, GEMM_DSM);
    cudaFuncSetAttribute(gemm_mma<true,  false, true >, cudaFuncAttributeMaxDynamicSharedMemorySize, GEMM_DSM);

    // 1-2. weight casts (merged)
    cast_ab_kernel<<<4096, 256>>>(w_qkv, w_out);
    cast_cd_kernel<<<8192, 256>>>(w1, w2);
    // 3. ln1 -> g_ln (fp16)
    ln_h_kernel<<<MROWS, 256>>>(x, 0, ln1_g, ln1_b);
    // 4. qkv = ln1 @ wqkv + b_qkv -> g_qkvh (fp16)
    gemm_mma<false, false, true><<<dim3(24, 32), 256, GEMM_DSM>>>(
        3072, 1024, 1, 3, b_qkv, nullptr, 0, nullptr, 8);
    // 5. HMMA attention -> g_ctx (fp16)
    attn_kernel<<<dim3(16, 16, 2), 256>>>(respos);
    // 6. x1 = x + ctx @ wout + b_out -> g_x1 (fp32)   [ncu capture slot]
    gemm_mma<false, true, false><<<dim3(8, 32), 256, GEMM_DSM>>>(
        1024, 1024, 2, 4, b_out, x, 0, nullptr, 2);
    // 7. ln2 -> g_ln
    ln_h_kernel<<<MROWS, 256>>>(nullptr, 2, ln2_g, ln2_b);
    // 8. ffn1 = relu(ln2 @ w1 + b1) -> g_ffn1 (fp16)
    gemm_mma<true, false, true><<<dim3(32, 32), 256, GEMM_DSM>>>(
        4096, 1024, 1, 5, b1, nullptr, 0, nullptr, 7);
    // 9. out = x1 + ffn1 @ w2 + b2 -> d_out (fp32)
    gemm_mma<false, true, false><<<dim3(8, 32), 256, GEMM_DSM>>>(
        1024, 4096, 7, 6, b2, nullptr, 2, out, 0);
}

// round 11
// speedup vs baseline: 1.2757x; 1.2757x over previous
#include <cuda_runtime.h>
#include <cuda_fp16.h>
#include <stdint.h>
#include <math.h>

#define MROWS 4096

// ---------------- scratch (fp16 operands) ----------------
__device__ __half g_ln  [(size_t)MROWS * 1024];
__device__ __half g_ctx [(size_t)MROWS * 1024];
__device__ __half g_wqkv[(size_t)1024 * 3072];
__device__ __half g_wout[(size_t)1024 * 1024];
__device__ __half g_w1  [(size_t)1024 * 4096];
__device__ __half g_w2  [(size_t)4096 * 1024];
__device__ __half g_ffn1[(size_t)MROWS * 4096];
__device__ __half g_qkvh[(size_t)MROWS * 3072];
__device__ float  g_x1  [(size_t)MROWS * 1024];

__device__ __forceinline__ const __half* bufh(int c)
{
    switch (c) {
        case 1: return g_ln;
        case 2: return g_ctx;
        case 3: return g_wqkv;
        case 4: return g_wout;
        case 5: return g_w1;
        case 6: return g_w2;
        case 7: return g_ffn1;
        default: return g_qkvh;
    }
}
__device__ __forceinline__ float* buff(int c, const float* p)
{
    switch (c) {
        case 2: return g_x1;
        default: return (float*)p;
    }
}

// ---------------- PTX helpers (baseline PTX; safe on plain sm_103) ----------
__device__ __forceinline__ uint32_t smem_u32(const void* p)
{
    uint32_t a;
    asm("{ .reg .u64 t; cvta.to.shared.u64 t, %1; cvt.u32.u64 %0, t; }" : "=r"(a) : "l"(p));
    return a;
}
__device__ __forceinline__ void ldm_x4(uint32_t* r, uint32_t a)
{
    asm volatile("ldmatrix.sync.aligned.m8n8.x4.shared.b16 {%0,%1,%2,%3}, [%4];"
        : "=r"(r[0]), "=r"(r[1]), "=r"(r[2]), "=r"(r[3]) : "r"(a));
}
__device__ __forceinline__ void ldm_x4_t(uint32_t* r, uint32_t a)
{
    asm volatile("ldmatrix.sync.aligned.m8n8.x4.trans.shared.b16 {%0,%1,%2,%3}, [%4];"
        : "=r"(r[0]), "=r"(r[1]), "=r"(r[2]), "=r"(r[3]) : "r"(a));
}
__device__ __forceinline__ void mma_f16(float* c, const uint32_t* a, const uint32_t* b)
{
    asm volatile("mma.sync.aligned.m16n8k16.row.col.f32.f16.f16.f32 "
        "{%0,%1,%2,%3}, {%4,%5,%6,%7}, {%8,%9}, {%0,%1,%2,%3};"
        : "+f"(c[0]), "+f"(c[1]), "+f"(c[2]), "+f"(c[3])
        : "r"(a[0]), "r"(a[1]), "r"(a[2]), "r"(a[3]), "r"(b[0]), "r"(b[1]));
}
__device__ __forceinline__ void cpa16(uint32_t s, const void* g)
{
    asm volatile("cp.async.cg.shared.global [%0], [%1], 16;" :: "r"(s), "l"(g));
}
#define CPA_COMMIT() asm volatile("cp.async.commit_group;" ::: "memory")
#define CPA_WAIT(n)  asm volatile("cp.async.wait_group %0;" :: "n"(n) : "memory")

// ---------------- merged weight casts: f32 -> f16 ----------------
__global__ __launch_bounds__(256) void cast_ab_kernel(const float* __restrict__ wqkv,
                                                      const float* __restrict__ wout)
{
    const int bid = blockIdx.x;
    const float* src = (bid < 3072) ? wqkv : wout;
    __half* dst = (bid < 3072) ? g_wqkv : g_wout;
    const size_t i = (size_t)(bid < 3072 ? bid : bid - 3072) * 256 + threadIdx.x;
    const float4 v = reinterpret_cast<const float4*>(src)[i];
    *(__half2*)&dst[i * 4]     = __floats2half2_rn(v.x, v.y);
    *(__half2*)&dst[i * 4 + 2] = __floats2half2_rn(v.z, v.w);
}
__global__ __launch_bounds__(256) void cast_cd_kernel(const float* __restrict__ w1,
                                                      const float* __restrict__ w2)
{
    const int bid = blockIdx.x;
    const float* src = (bid < 4096) ? w1 : w2;
    __half* dst = (bid < 4096) ? g_w1 : g_w2;
    const size_t i = (size_t)(bid < 4096 ? bid : bid - 4096) * 256 + threadIdx.x;
    const float4 v = reinterpret_cast<const float4*>(src)[i];
    *(__half2*)&dst[i * 4]     = __floats2half2_rn(v.x, v.y);
    *(__half2*)&dst[i * 4 + 2] = __floats2half2_rn(v.z, v.w);
}

// ---------------- LayerNorm -> fp16 [row, 1024] ----------------
__global__ __launch_bounds__(256) void ln_h_kernel(const float* __restrict__ xp, int xc,
                                                   const float* __restrict__ gam,
                                                   const float* __restrict__ bet)
{
    const float* x = buff(xc, xp);
    __shared__ float sh[8];
    __shared__ float stat[2];
    const int row = blockIdx.x, t = threadIdx.x;

    const float4 v = reinterpret_cast<const float4*>(x)[(size_t)row * 256 + t];
    float s = v.x + v.y + v.z + v.w;
    #pragma unroll
    for (int o = 16; o; o >>= 1) s += __shfl_xor_sync(0xffffffffu, s, o);
    if ((t & 31) == 0) sh[t >> 5] = s;
    __syncthreads();
    if (t < 32) {
        float u = (t < 8) ? sh[t] : 0.f;
        #pragma unroll
        for (int o = 4; o; o >>= 1) u += __shfl_xor_sync(0xffffffffu, u, o);
        if (t == 0) stat[0] = u * (1.f / 1024.f);
    }
    __syncthreads();
    const float mu = stat[0];
    const float a = v.x - mu, b = v.y - mu, c = v.z - mu, d = v.w - mu;
    float s2 = a * a + b * b + c * c + d * d;
    #pragma unroll
    for (int o = 16; o; o >>= 1) s2 += __shfl_xor_sync(0xffffffffu, s2, o);
    if ((t & 31) == 0) sh[t >> 5] = s2;
    __syncthreads();
    if (t < 32) {
        float u = (t < 8) ? sh[t] : 0.f;
        #pragma unroll
        for (int o = 4; o; o >>= 1) u += __shfl_xor_sync(0xffffffffu, u, o);
        if (t == 0) stat[1] = rsqrtf(u * (1.f / 1024.f) + 1e-5f);
    }
    __syncthreads();
    const float inv = stat[1];
    const float4 gv = *(const float4*)(gam + t * 4);
    const float4 bv = *(const float4*)(bet + t * 4);
    const float o0 = a * inv * gv.x + bv.x, o1 = b * inv * gv.y + bv.y;
    const float o2 = c * inv * gv.z + bv.z, o3 = d * inv * gv.w + bv.w;
    const size_t base = (size_t)row * 1024 + t * 4;
    *(__half2*)&g_ln[base]     = __floats2half2_rn(o0, o1);
    *(__half2*)&g_ln[base + 2] = __floats2half2_rn(o2, o3);
}

// ---------------- HMMA fp16 GEMM (cp.async 3-stage BK=32, 48KB static) -------
// CTA 128x128, 256 thr, 8 warps (4m x 2n), warp 32x64 (2x8 m16n8k16).
// Stage = A[128x32] (8KB, chunk swz c^((r>>1)&3)) + B[32x128] (8KB, c^(k&7)).
template<bool RELU, bool RESID, bool HALFOUT>
__global__ __launch_bounds__(256) void gemm_mma(
    int N, int KTOT, int Ac, int Bc,
    const float* __restrict__ bias,
    const float* resp, int resc,
    float* Cp, int Cc)
{
    const __half* A  = bufh(Ac);
    const __half* Bw = bufh(Bc);
    const float* res = buff(resc, resp);
    float* C = HALFOUT ? nullptr : buff(Cc, Cp);
    __half* Ch = HALFOUT ? (__half*)bufh(Cc) : nullptr;

    __shared__ __align__(16) char smem3[3][16384];

    const int tid = threadIdx.x;
    const int wid = tid >> 5, lane = tid & 31;
    const int wm = wid & 3, wn = wid >> 2;
    const int brow = blockIdx.y, bcol = blockIdx.x;

    const __half* Ablk = A + (size_t)(brow * 128) * KTOT;
    const __half* Bblk = Bw + bcol * 128;

    const uint32_t smB = smem_u32(smem3);

    const int ar = tid >> 2, acn = tid & 3;
    const int bk = tid >> 4, bcn = tid & 15;
    const uint32_t aso0 = (uint32_t)(ar * 64  + ((acn ^ ((ar >> 1) & 3)) << 4));
    const uint32_t aso1 = (uint32_t)((ar + 64) * 64 + ((acn ^ (((ar + 64) >> 1) & 3)) << 4));
    const uint32_t bso0 = (uint32_t)(8192 + bk * 256 + ((bcn ^ (bk & 7)) << 4));
    const uint32_t bso1 = (uint32_t)(8192 + (bk + 16) * 256 + ((bcn ^ ((bk + 16) & 7)) << 4));

    const int lr = lane & 15, lc = lane >> 4;
    const int arow[2] = { wm * 32 + lr, wm * 32 + 16 + lr };
    const uint32_t aswz[2] = { (uint32_t)((arow[0] >> 1) & 3), (uint32_t)((arow[1] >> 1) & 3) };
    const uint32_t bswzk = (uint32_t)(lr & 7);

    float acc[2][8][4];
    #pragma unroll
    for (int mt = 0; mt < 2; mt++)
        #pragma unroll
        for (int nt = 0; nt < 8; nt++)
            #pragma unroll
            for (int q = 0; q < 4; q++) acc[mt][nt][q] = 0.f;

    const int NS = KTOT >> 5;

    auto issue = [&](int ss) {
        const int kg = ss * 32;
        const uint32_t st = smB + (uint32_t)((ss % 3) * 16384);
        cpa16(st + aso0, Ablk + (size_t)ar * KTOT + kg + acn * 8);
        cpa16(st + aso1, Ablk + (size_t)(ar + 64) * KTOT + kg + acn * 8);
        cpa16(st + bso0, Bblk + (size_t)(kg + bk) * N + bcn * 8);
        cpa16(st + bso1, Bblk + (size_t)(kg + bk + 16) * N + bcn * 8);
        CPA_COMMIT();
    };

    issue(0);
    issue(1);

    #pragma unroll 1
    for (int s = 0; s < NS; s++) {
        if (s + 1 < NS) { CPA_WAIT(1); } else { CPA_WAIT(0); }
        __syncthreads();
        if (s + 2 < NS) issue(s + 2);

        const uint32_t aB = smB + (uint32_t)((s % 3) * 16384);
        const uint32_t bB = aB + 8192;
        #pragma unroll
        for (int ks = 0; ks < 2; ks++) {
            uint32_t af[2][4], bf[4][4];
            #pragma unroll
            for (int mt = 0; mt < 2; mt++) {
                const uint32_t chunk = ((uint32_t)(ks * 2 + lc)) ^ aswz[mt];
                ldm_x4(af[mt], aB + (uint32_t)(arow[mt] * 64) + (chunk << 4));
            }
            const uint32_t kk = (uint32_t)(ks * 16 + lr);
            #pragma unroll
            for (int n16 = 0; n16 < 4; n16++) {
                const uint32_t cn = ((uint32_t)(wn * 8 + n16 * 2 + lc)) ^ bswzk;
                ldm_x4_t(bf[n16], bB + kk * 256 + (cn << 4));
            }
            #pragma unroll
            for (int mt = 0; mt < 2; mt++)
                #pragma unroll
                for (int nt = 0; nt < 8; nt++)
                    mma_f16(acc[mt][nt], af[mt], &bf[nt >> 1][(nt & 1) * 2]);
        }
    }

    const int rbase = brow * 128 + wm * 32 + (lane >> 2);
    const int cbase = bcol * 128 + wn * 64 + (lane & 3) * 2;
    #pragma unroll
    for (int mt = 0; mt < 2; mt++) {
        #pragma unroll
        for (int nt = 0; nt < 8; nt++) {
            const int c = cbase + nt * 8;
            const float2 bv = *(const float2*)(bias + c);
            #pragma unroll
            for (int hrow = 0; hrow < 2; hrow++) {
                const int r = rbase + mt * 16 + hrow * 8;
                float v0 = acc[mt][nt][hrow * 2]     + bv.x;
                float v1 = acc[mt][nt][hrow * 2 + 1] + bv.y;
                if (HALFOUT) {
                    if (RELU) { v0 = fmaxf(v0, 0.f); v1 = fmaxf(v1, 0.f); }
                    *(__half2*)&Ch[(size_t)r * N + c] = __floats2half2_rn(v0, v1);
                } else {
                    const size_t off = (size_t)r * N + c;
                    if (RESID) {
                        const float2 rv = *(const float2*)(res + off);
                        v0 += rv.x; v1 += rv.y;
                    }
                    float2 ov; ov.x = v0; ov.y = v1;
                    *(float2*)(C + off) = ov;
                }
            }
        }
    }
}

// ---------------- HMMA windowed flash attention -> g_ctx (fp16) --------------
__global__ __launch_bounds__(256) void attn_kernel(const float* __restrict__ res_pos)
{
    __shared__ __align__(16) __half Qs[128 * 64];
    __shared__ __align__(16) __half Ks[64 * 64];
    __shared__ __align__(16) __half Vs[64 * 64];
    __shared__ float rp[512];

    const __half* qkv = g_qkvh;
    const int bx = blockIdx.x, h = blockIdx.y, bb = blockIdx.z;
    const int q0 = bx * 128;
    const int tid = threadIdx.x, wid = tid >> 5, lane = tid & 31;
    const int lr = lane & 15, lc = lane >> 4;
    const int r0 = lane >> 2;

    const uint32_t qsB = smem_u32(Qs);
    const uint32_t ksB = smem_u32(Ks);
    const uint32_t vsB = smem_u32(Vs);

    for (int i = tid; i < 512; i += 256) rp[i] = res_pos[h * 512 + i];

    #pragma unroll
    for (int i = 0; i < 4; i++) {
        const int idx = i * 256 + tid;
        const int r = idx >> 3, c = idx & 7;
        *(uint4*)((char*)Qs + r * 128 + (((uint32_t)c ^ (r & 7)) << 4)) =
            *(const uint4*)(qkv + (size_t)(bb * 2048 + q0 + r) * 3072 + h * 64 + c * 8);
    }
    __syncthreads();

    uint32_t qf[4][4];
    #pragma unroll
    for (int ks = 0; ks < 4; ks++) {
        const int row = wid * 16 + lr;
        const uint32_t chunk = ((uint32_t)(2 * ks + lc)) ^ (row & 7);
        ldm_x4(qf[ks], qsB + (uint32_t)(row * 128) + (chunk << 4));
    }

    float m0 = -1e30f, m8 = -1e30f, l0 = 0.f, l8 = 0.f;
    float of[8][4];
    #pragma unroll
    for (int nt = 0; nt < 8; nt++)
        #pragma unroll
        for (int q = 0; q < 4; q++) of[nt][q] = 0.f;

    const int ktlo = (q0 >= 511) ? ((q0 - 511) >> 6) : 0;
    const int kthi = (q0 + 127) >> 6;

    for (int kt = ktlo; kt <= kthi; kt++) {
        __syncthreads();
        #pragma unroll
        for (int i = 0; i < 4; i++) {
            const int idx = i * 256 + tid;
            const int arr = idx >> 9, rem = idx & 511;
            const int r = rem >> 3, c = rem & 7;
            const uint4 v = *(const uint4*)(qkv + (size_t)(bb * 2048 + kt * 64 + r) * 3072
                                            + 1024 + arr * 1024 + h * 64 + c * 8);
            char* dst = arr ? (char*)Vs : (char*)Ks;
            *(uint4*)(dst + r * 128 + (((uint32_t)c ^ (r & 7)) << 4)) = v;
        }
        __syncthreads();

        float sc[8][4];
        #pragma unroll
        for (int nt = 0; nt < 8; nt++)
            #pragma unroll
            for (int q = 0; q < 4; q++) sc[nt][q] = 0.f;
        #pragma unroll
        for (int cd = 0; cd < 4; cd++) {
            uint32_t kb[4][4];
            #pragma unroll
            for (int g = 0; g < 4; g++) {
                const int kr = g * 16 + lr;
                const uint32_t chunk = ((uint32_t)(2 * cd + lc)) ^ (kr & 7);
                ldm_x4(kb[g], ksB + (uint32_t)(kr * 128) + (chunk << 4));
            }
            #pragma unroll
            for (int nt = 0; nt < 8; nt++) {
                uint32_t bp[2];
                const int g = nt >> 1;
                if (nt & 1) { bp[0] = kb[g][1]; bp[1] = kb[g][3]; }
                else        { bp[0] = kb[g][0]; bp[1] = kb[g][2]; }
                mma_f16(sc[nt], qf[cd], bp);
            }
        }

        const int qr = q0 + wid * 16 + r0;
        #pragma unroll
        for (int nt = 0; nt < 8; nt++) {
            const int key0 = kt * 64 + nt * 8 + (lane & 3) * 2;
            #pragma unroll
            for (int j = 0; j < 2; j++) {
                const int dd  = qr - (key0 + j);
                const int dd8 = dd + 8;
                sc[nt][j]     = (dd  >= 0 && dd  < 512) ? sc[nt][j]     * 0.125f + rp[dd]  : -1e30f;
                sc[nt][2 + j] = (dd8 >= 0 && dd8 < 512) ? sc[nt][2 + j] * 0.125f + rp[dd8] : -1e30f;
            }
        }

        float t0 = -1e30f, t8 = -1e30f;
        #pragma unroll
        for (int nt = 0; nt < 8; nt++) {
            t0 = fmaxf(t0, fmaxf(sc[nt][0], sc[nt][1]));
            t8 = fmaxf(t8, fmaxf(sc[nt][2], sc[nt][3]));
        }
        #pragma unroll
        for (int o = 1; o <= 2; o <<= 1) {
            t0 = fmaxf(t0, __shfl_xor_sync(0xffffffffu, t0, o));
            t8 = fmaxf(t8, __shfl_xor_sync(0xffffffffu, t8, o));
        }
        const float mn0 = fmaxf(m0, t0), mn8 = fmaxf(m8, t8);
        const float al0 = __expf(m0 - mn0), al8 = __expf(m8 - mn8);
        m0 = mn0; m8 = mn8;
        float rs0 = 0.f, rs8 = 0.f;
        #pragma unroll
        for (int nt = 0; nt < 8; nt++) {
            sc[nt][0] = __expf(sc[nt][0] - mn0); rs0 += sc[nt][0];
            sc[nt][1] = __expf(sc[nt][1] - mn0); rs0 += sc[nt][1];
            sc[nt][2] = __expf(sc[nt][2] - mn8); rs8 += sc[nt][2];
            sc[nt][3] = __expf(sc[nt][3] - mn8); rs8 += sc[nt][3];
        }
        #pragma unroll
        for (int o = 1; o <= 2; o <<= 1) {
            rs0 += __shfl_xor_sync(0xffffffffu, rs0, o);
            rs8 += __shfl_xor_sync(0xffffffffu, rs8, o);
        }
        l0 = l0 * al0 + rs0;
        l8 = l8 * al8 + rs8;
        #pragma unroll
        for (int nt = 0; nt < 8; nt++) {
            of[nt][0] *= al0; of[nt][1] *= al0;
            of[nt][2] *= al8; of[nt][3] *= al8;
        }

        #pragma unroll
        for (int ks = 0; ks < 4; ks++) {
            uint32_t ap[4];
            __half2 h0 = __floats2half2_rn(sc[2 * ks][0],     sc[2 * ks][1]);
            __half2 h1 = __floats2half2_rn(sc[2 * ks][2],     sc[2 * ks][3]);
            __half2 h2 = __floats2half2_rn(sc[2 * ks + 1][0], sc[2 * ks + 1][1]);
            __half2 h3 = __floats2half2_rn(sc[2 * ks + 1][2], sc[2 * ks + 1][3]);
            ap[0] = *(uint32_t*)&h0; ap[1] = *(uint32_t*)&h1;
            ap[2] = *(uint32_t*)&h2; ap[3] = *(uint32_t*)&h3;
            uint32_t vb[4][4];
            const int kk = ks * 16 + lr;
            #pragma unroll
            for (int nv = 0; nv < 4; nv++) {
                const uint32_t cn = ((uint32_t)(2 * nv + lc)) ^ (kk & 7);
                ldm_x4_t(vb[nv], vsB + (uint32_t)(kk * 128) + (cn << 4));
            }
            #pragma unroll
            for (int nt = 0; nt < 8; nt++)
                mma_f16(of[nt], ap, &vb[nt >> 1][(nt & 1) * 2]);
        }
    }

    const float rl0 = 1.f / l0, rl8 = 1.f / l8;
    const int rowA = bb * 2048 + q0 + wid * 16 + r0;
    #pragma unroll
    for (int nt = 0; nt < 8; nt++) {
        const int c = h * 64 + nt * 8 + (lane & 3) * 2;
        *(__half2*)&g_ctx[(size_t)rowA * 1024 + c] =
            __floats2half2_rn(of[nt][0] * rl0, of[nt][1] * rl0);
        *(__half2*)&g_ctx[(size_t)(rowA + 8) * 1024 + c] =
            __floats2half2_rn(of[nt][2] * rl8, of[nt][3] * rl8);
    }
}

// ---------------- launch: kernel launches ONLY ----------------
extern "C" void kernel_launch(void* const* d_in, const int* in_sizes, int n_in,
                              void* d_out, int out_size)
{
    (void)in_sizes; (void)n_in; (void)out_size;
    const float* x      = (const float*)d_in[0];
    const float* respos = (const float*)d_in[1];
    const float* w_qkv  = (const float*)d_in[2];
    const float* b_qkv  = (const float*)d_in[3];
    const float* w_out  = (const float*)d_in[4];
    const float* b_out  = (const float*)d_in[5];
    const float* w1     = (const float*)d_in[6];
    const float* b1     = (const float*)d_in[7];
    const float* w2     = (const float*)d_in[8];
    const float* b2     = (const float*)d_in[9];
    const float* ln1_g  = (const float*)d_in[10];
    const float* ln1_b  = (const float*)d_in[11];
    const float* ln2_g  = (const float*)d_in[12];
    const float* ln2_b  = (const float*)d_in[13];
    float* out = (float*)d_out;

    // 1-2. merged weight casts
    cast_ab_kernel<<<4096, 256>>>(w_qkv, w_out);
    cast_cd_kernel<<<8192, 256>>>(w1, w2);
    // 3. ln1 -> g_ln (fp16)
    ln_h_kernel<<<MROWS, 256>>>(x, 0, ln1_g, ln1_b);
    // 4. qkv = ln1 @ wqkv + b_qkv -> g_qkvh (fp16)
    gemm_mma<false, false, true><<<dim3(24, 32), 256>>>(
        3072, 1024, 1, 3, b_qkv, nullptr, 0, nullptr, 8);
    // 5. HMMA attention -> g_ctx (fp16)
    attn_kernel<<<dim3(16, 16, 2), 256>>>(respos);
    // 6. x1 = x + ctx @ wout + b_out -> g_x1 (fp32)   [ncu capture slot]
    gemm_mma<false, true, false><<<dim3(8, 32), 256>>>(
        1024, 1024, 2, 4, b_out, x, 0, nullptr, 2);
    // 7. ln2 -> g_ln
    ln_h_kernel<<<MROWS, 256>>>(nullptr, 2, ln2_g, ln2_b);
    // 8. ffn1 = relu(ln2 @ w1 + b1) -> g_ffn1 (fp16)
    gemm_mma<true, false, true><<<dim3(32, 32), 256>>>(
        4096, 1024, 1, 5, b1, nullptr, 0, nullptr, 7);
    // 9. out = x1 + ffn1 @ w2 + b2 -> d_out (fp32)
    gemm_mma<false, true, false><<<dim3(8, 32), 256>>>(
        1024, 4096, 7, 6, b2, nullptr, 2, out, 0);
}

// round 12
// speedup vs baseline: 1.3568x; 1.0635x over previous
#include <cuda_runtime.h>
#include <cuda_fp16.h>
#include <stdint.h>
#include <math.h>

#define MROWS 4096

// ---------------- scratch (fp16 operands) ----------------
__device__ __half g_ln  [(size_t)MROWS * 1024];
__device__ __half g_ctx [(size_t)MROWS * 1024];
__device__ __half g_wqkv[(size_t)1024 * 3072];
__device__ __half g_wout[(size_t)1024 * 1024];
__device__ __half g_w1  [(size_t)1024 * 4096];
__device__ __half g_w2  [(size_t)4096 * 1024];
__device__ __half g_ffn1[(size_t)MROWS * 4096];
__device__ __half g_qkvh[(size_t)MROWS * 3072];
__device__ float  g_x1  [(size_t)MROWS * 1024];

__device__ __forceinline__ const __half* bufh(int c)
{
    switch (c) {
        case 1: return g_ln;
        case 2: return g_ctx;
        case 3: return g_wqkv;
        case 4: return g_wout;
        case 5: return g_w1;
        case 6: return g_w2;
        case 7: return g_ffn1;
        default: return g_qkvh;
    }
}
__device__ __forceinline__ float* buff(int c, const float* p)
{
    switch (c) {
        case 2: return g_x1;
        default: return (float*)p;
    }
}

// ---------------- PTX helpers (baseline PTX; safe on plain sm_103) ----------
__device__ __forceinline__ uint32_t smem_u32(const void* p)
{
    uint32_t a;
    asm("{ .reg .u64 t; cvta.to.shared.u64 t, %1; cvt.u32.u64 %0, t; }" : "=r"(a) : "l"(p));
    return a;
}
__device__ __forceinline__ void ldm_x4(uint32_t* r, uint32_t a)
{
    asm volatile("ldmatrix.sync.aligned.m8n8.x4.shared.b16 {%0,%1,%2,%3}, [%4];"
        : "=r"(r[0]), "=r"(r[1]), "=r"(r[2]), "=r"(r[3]) : "r"(a));
}
__device__ __forceinline__ void ldm_x4_t(uint32_t* r, uint32_t a)
{
    asm volatile("ldmatrix.sync.aligned.m8n8.x4.trans.shared.b16 {%0,%1,%2,%3}, [%4];"
        : "=r"(r[0]), "=r"(r[1]), "=r"(r[2]), "=r"(r[3]) : "r"(a));
}
__device__ __forceinline__ void mma_f16(float* c, const uint32_t* a, const uint32_t* b)
{
    asm volatile("mma.sync.aligned.m16n8k16.row.col.f32.f16.f16.f32 "
        "{%0,%1,%2,%3}, {%4,%5,%6,%7}, {%8,%9}, {%0,%1,%2,%3};"
        : "+f"(c[0]), "+f"(c[1]), "+f"(c[2]), "+f"(c[3])
        : "r"(a[0]), "r"(a[1]), "r"(a[2]), "r"(a[3]), "r"(b[0]), "r"(b[1]));
}
__device__ __forceinline__ void cpa16(uint32_t s, const void* g)
{
    asm volatile("cp.async.cg.shared.global [%0], [%1], 16;" :: "r"(s), "l"(g));
}
#define CPA_COMMIT() asm volatile("cp.async.commit_group;" ::: "memory")
#define CPA_WAIT(n)  asm volatile("cp.async.wait_group %0;" :: "n"(n) : "memory")

// ---------------- single merged weight cast: f32 -> f16 ----------------
__global__ __launch_bounds__(256) void cast_all_kernel(const float* __restrict__ wqkv,
                                                       const float* __restrict__ wout,
                                                       const float* __restrict__ w1,
                                                       const float* __restrict__ w2)
{
    const int bid = blockIdx.x;
    const float* src;
    __half* dst;
    int lb;
    if (bid < 3072)      { src = wqkv; dst = g_wqkv; lb = bid; }
    else if (bid < 4096) { src = wout; dst = g_wout; lb = bid - 3072; }
    else if (bid < 8192) { src = w1;   dst = g_w1;   lb = bid - 4096; }
    else                 { src = w2;   dst = g_w2;   lb = bid - 8192; }
    const size_t i = (size_t)lb * 256 + threadIdx.x;
    const float4 v = reinterpret_cast<const float4*>(src)[i];
    *(__half2*)&dst[i * 4]     = __floats2half2_rn(v.x, v.y);
    *(__half2*)&dst[i * 4 + 2] = __floats2half2_rn(v.z, v.w);
}

// ---------------- LayerNorm -> fp16 [row, 1024] ----------------
__global__ __launch_bounds__(256) void ln_h_kernel(const float* __restrict__ xp, int xc,
                                                   const float* __restrict__ gam,
                                                   const float* __restrict__ bet)
{
    const float* x = buff(xc, xp);
    __shared__ float sh[8];
    __shared__ float stat[2];
    const int row = blockIdx.x, t = threadIdx.x;

    const float4 v = reinterpret_cast<const float4*>(x)[(size_t)row * 256 + t];
    float s = v.x + v.y + v.z + v.w;
    #pragma unroll
    for (int o = 16; o; o >>= 1) s += __shfl_xor_sync(0xffffffffu, s, o);
    if ((t & 31) == 0) sh[t >> 5] = s;
    __syncthreads();
    if (t < 32) {
        float u = (t < 8) ? sh[t] : 0.f;
        #pragma unroll
        for (int o = 4; o; o >>= 1) u += __shfl_xor_sync(0xffffffffu, u, o);
        if (t == 0) stat[0] = u * (1.f / 1024.f);
    }
    __syncthreads();
    const float mu = stat[0];
    const float a = v.x - mu, b = v.y - mu, c = v.z - mu, d = v.w - mu;
    float s2 = a * a + b * b + c * c + d * d;
    #pragma unroll
    for (int o = 16; o; o >>= 1) s2 += __shfl_xor_sync(0xffffffffu, s2, o);
    if ((t & 31) == 0) sh[t >> 5] = s2;
    __syncthreads();
    if (t < 32) {
        float u = (t < 8) ? sh[t] : 0.f;
        #pragma unroll
        for (int o = 4; o; o >>= 1) u += __shfl_xor_sync(0xffffffffu, u, o);
        if (t == 0) stat[1] = rsqrtf(u * (1.f / 1024.f) + 1e-5f);
    }
    __syncthreads();
    const float inv = stat[1];
    const float4 gv = *(const float4*)(gam + t * 4);
    const float4 bv = *(const float4*)(bet + t * 4);
    const float o0 = a * inv * gv.x + bv.x, o1 = b * inv * gv.y + bv.y;
    const float o2 = c * inv * gv.z + bv.z, o3 = d * inv * gv.w + bv.w;
    const size_t base = (size_t)row * 1024 + t * 4;
    *(__half2*)&g_ln[base]     = __floats2half2_rn(o0, o1);
    *(__half2*)&g_ln[base + 2] = __floats2half2_rn(o2, o3);
}

// ---------------- HMMA fp16 GEMM (cp.async 4-stage BK=32, 64KB dynamic) ------
// CTA 128x128, 256 thr, 8 warps (4m x 2n), warp 32x64 (2x8 m16n8k16).
// Stage = A[128x32] (8KB, chunk swz c^((r>>1)&3)) + B[32x128] (8KB, c^(k&7)).
// __launch_bounds__(256,2) caps regs at 128 -> guaranteed 2 CTA/SM.
#define GEMM_DSM (4 * 16384)

template<bool RELU, bool RESID, bool HALFOUT>
__global__ __launch_bounds__(256, 2) void gemm_mma(
    int N, int KTOT, int Ac, int Bc,
    const float* __restrict__ bias,
    const float* resp, int resc,
    float* Cp, int Cc)
{
    const __half* A  = bufh(Ac);
    const __half* Bw = bufh(Bc);
    const float* res = buff(resc, resp);
    float* C = HALFOUT ? nullptr : buff(Cc, Cp);
    __half* Ch = HALFOUT ? (__half*)bufh(Cc) : nullptr;

    extern __shared__ __align__(16) char dsm[];

    const int tid = threadIdx.x;
    const int wid = tid >> 5, lane = tid & 31;
    const int wm = wid & 3, wn = wid >> 2;
    const int brow = blockIdx.y, bcol = blockIdx.x;

    const __half* Ablk = A + (size_t)(brow * 128) * KTOT;
    const __half* Bblk = Bw + bcol * 128;

    const uint32_t smB = smem_u32(dsm);

    const int ar = tid >> 2, acn = tid & 3;
    const int bk = tid >> 4, bcn = tid & 15;
    const uint32_t aso0 = (uint32_t)(ar * 64  + ((acn ^ ((ar >> 1) & 3)) << 4));
    const uint32_t aso1 = (uint32_t)((ar + 64) * 64 + ((acn ^ (((ar + 64) >> 1) & 3)) << 4));
    const uint32_t bso0 = (uint32_t)(8192 + bk * 256 + ((bcn ^ (bk & 7)) << 4));
    const uint32_t bso1 = (uint32_t)(8192 + (bk + 16) * 256 + ((bcn ^ ((bk + 16) & 7)) << 4));

    const int lr = lane & 15, lc = lane >> 4;
    const int arow[2] = { wm * 32 + lr, wm * 32 + 16 + lr };
    const uint32_t aswz[2] = { (uint32_t)((arow[0] >> 1) & 3), (uint32_t)((arow[1] >> 1) & 3) };
    const uint32_t bswzk = (uint32_t)(lr & 7);

    float acc[2][8][4];
    #pragma unroll
    for (int mt = 0; mt < 2; mt++)
        #pragma unroll
        for (int nt = 0; nt < 8; nt++)
            #pragma unroll
            for (int q = 0; q < 4; q++) acc[mt][nt][q] = 0.f;

    const int NS = KTOT >> 5;

    auto issue = [&](int ss) {
        const int kg = ss * 32;
        const uint32_t st = smB + (uint32_t)((ss & 3) * 16384);
        cpa16(st + aso0, Ablk + (size_t)ar * KTOT + kg + acn * 8);
        cpa16(st + aso1, Ablk + (size_t)(ar + 64) * KTOT + kg + acn * 8);
        cpa16(st + bso0, Bblk + (size_t)(kg + bk) * N + bcn * 8);
        cpa16(st + bso1, Bblk + (size_t)(kg + bk + 16) * N + bcn * 8);
        CPA_COMMIT();
    };

    issue(0);
    issue(1);
    issue(2);

    #pragma unroll 1
    for (int s = 0; s < NS; s++) {
        if (s + 2 < NS) { CPA_WAIT(2); } else { CPA_WAIT(0); }
        __syncthreads();                   // stage s visible; compute s-1 retired
        if (s + 3 < NS) issue(s + 3);      // writes buffer (s-1)&3 — safe after sync

        const uint32_t aB = smB + (uint32_t)((s & 3) * 16384);
        const uint32_t bB = aB + 8192;
        #pragma unroll
        for (int ks = 0; ks < 2; ks++) {
            uint32_t af[2][4], bf[4][4];
            #pragma unroll
            for (int mt = 0; mt < 2; mt++) {
                const uint32_t chunk = ((uint32_t)(ks * 2 + lc)) ^ aswz[mt];
                ldm_x4(af[mt], aB + (uint32_t)(arow[mt] * 64) + (chunk << 4));
            }
            const uint32_t kk = (uint32_t)(ks * 16 + lr);
            #pragma unroll
            for (int n16 = 0; n16 < 4; n16++) {
                const uint32_t cn = ((uint32_t)(wn * 8 + n16 * 2 + lc)) ^ bswzk;
                ldm_x4_t(bf[n16], bB + kk * 256 + (cn << 4));
            }
            #pragma unroll
            for (int mt = 0; mt < 2; mt++)
                #pragma unroll
                for (int nt = 0; nt < 8; nt++)
                    mma_f16(acc[mt][nt], af[mt], &bf[nt >> 1][(nt & 1) * 2]);
        }
    }

    const int rbase = brow * 128 + wm * 32 + (lane >> 2);
    const int cbase = bcol * 128 + wn * 64 + (lane & 3) * 2;
    #pragma unroll
    for (int mt = 0; mt < 2; mt++) {
        #pragma unroll
        for (int nt = 0; nt < 8; nt++) {
            const int c = cbase + nt * 8;
            const float2 bv = *(const float2*)(bias + c);
            #pragma unroll
            for (int hrow = 0; hrow < 2; hrow++) {
                const int r = rbase + mt * 16 + hrow * 8;
                float v0 = acc[mt][nt][hrow * 2]     + bv.x;
                float v1 = acc[mt][nt][hrow * 2 + 1] + bv.y;
                if (HALFOUT) {
                    if (RELU) { v0 = fmaxf(v0, 0.f); v1 = fmaxf(v1, 0.f); }
                    *(__half2*)&Ch[(size_t)r * N + c] = __floats2half2_rn(v0, v1);
                } else {
                    const size_t off = (size_t)r * N + c;
                    if (RESID) {
                        const float2 rv = *(const float2*)(res + off);
                        v0 += rv.x; v1 += rv.y;
                    }
                    float2 ov; ov.x = v0; ov.y = v1;
                    *(float2*)(C + off) = ov;
                }
            }
        }
    }
}

// ---------------- HMMA windowed flash attention -> g_ctx (fp16) --------------
__global__ __launch_bounds__(256) void attn_kernel(const float* __restrict__ res_pos)
{
    __shared__ __align__(16) __half Qs[128 * 64];
    __shared__ __align__(16) __half Ks[64 * 64];
    __shared__ __align__(16) __half Vs[64 * 64];
    __shared__ float rp[512];

    const __half* qkv = g_qkvh;
    const int bx = blockIdx.x, h = blockIdx.y, bb = blockIdx.z;
    const int q0 = bx * 128;
    const int tid = threadIdx.x, wid = tid >> 5, lane = tid & 31;
    const int lr = lane & 15, lc = lane >> 4;
    const int r0 = lane >> 2;

    const uint32_t qsB = smem_u32(Qs);
    const uint32_t ksB = smem_u32(Ks);
    const uint32_t vsB = smem_u32(Vs);

    for (int i = tid; i < 512; i += 256) rp[i] = res_pos[h * 512 + i];

    #pragma unroll
    for (int i = 0; i < 4; i++) {
        const int idx = i * 256 + tid;
        const int r = idx >> 3, c = idx & 7;
        *(uint4*)((char*)Qs + r * 128 + (((uint32_t)c ^ (r & 7)) << 4)) =
            *(const uint4*)(qkv + (size_t)(bb * 2048 + q0 + r) * 3072 + h * 64 + c * 8);
    }
    __syncthreads();

    uint32_t qf[4][4];
    #pragma unroll
    for (int ks = 0; ks < 4; ks++) {
        const int row = wid * 16 + lr;
        const uint32_t chunk = ((uint32_t)(2 * ks + lc)) ^ (row & 7);
        ldm_x4(qf[ks], qsB + (uint32_t)(row * 128) + (chunk << 4));
    }

    float m0 = -1e30f, m8 = -1e30f, l0 = 0.f, l8 = 0.f;
    float of[8][4];
    #pragma unroll
    for (int nt = 0; nt < 8; nt++)
        #pragma unroll
        for (int q = 0; q < 4; q++) of[nt][q] = 0.f;

    const int ktlo = (q0 >= 511) ? ((q0 - 511) >> 6) : 0;
    const int kthi = (q0 + 127) >> 6;

    for (int kt = ktlo; kt <= kthi; kt++) {
        __syncthreads();
        #pragma unroll
        for (int i = 0; i < 4; i++) {
            const int idx = i * 256 + tid;
            const int arr = idx >> 9, rem = idx & 511;
            const int r = rem >> 3, c = rem & 7;
            const uint4 v = *(const uint4*)(qkv + (size_t)(bb * 2048 + kt * 64 + r) * 3072
                                            + 1024 + arr * 1024 + h * 64 + c * 8);
            char* dst = arr ? (char*)Vs : (char*)Ks;
            *(uint4*)(dst + r * 128 + (((uint32_t)c ^ (r & 7)) << 4)) = v;
        }
        __syncthreads();

        float sc[8][4];
        #pragma unroll
        for (int nt = 0; nt < 8; nt++)
            #pragma unroll
            for (int q = 0; q < 4; q++) sc[nt][q] = 0.f;
        #pragma unroll
        for (int cd = 0; cd < 4; cd++) {
            uint32_t kb[4][4];
            #pragma unroll
            for (int g = 0; g < 4; g++) {
                const int kr = g * 16 + lr;
                const uint32_t chunk = ((uint32_t)(2 * cd + lc)) ^ (kr & 7);
                ldm_x4(kb[g], ksB + (uint32_t)(kr * 128) + (chunk << 4));
            }
            #pragma unroll
            for (int nt = 0; nt < 8; nt++) {
                uint32_t bp[2];
                const int g = nt >> 1;
                if (nt & 1) { bp[0] = kb[g][1]; bp[1] = kb[g][3]; }
                else        { bp[0] = kb[g][0]; bp[1] = kb[g][2]; }
                mma_f16(sc[nt], qf[cd], bp);
            }
        }

        const int qr = q0 + wid * 16 + r0;
        #pragma unroll
        for (int nt = 0; nt < 8; nt++) {
            const int key0 = kt * 64 + nt * 8 + (lane & 3) * 2;
            #pragma unroll
            for (int j = 0; j < 2; j++) {
                const int dd  = qr - (key0 + j);
                const int dd8 = dd + 8;
                sc[nt][j]     = (dd  >= 0 && dd  < 512) ? sc[nt][j]     * 0.125f + rp[dd]  : -1e30f;
                sc[nt][2 + j] = (dd8 >= 0 && dd8 < 512) ? sc[nt][2 + j] * 0.125f + rp[dd8] : -1e30f;
            }
        }

        float t0 = -1e30f, t8 = -1e30f;
        #pragma unroll
        for (int nt = 0; nt < 8; nt++) {
            t0 = fmaxf(t0, fmaxf(sc[nt][0], sc[nt][1]));
            t8 = fmaxf(t8, fmaxf(sc[nt][2], sc[nt][3]));
        }
        #pragma unroll
        for (int o = 1; o <= 2; o <<= 1) {
            t0 = fmaxf(t0, __shfl_xor_sync(0xffffffffu, t0, o));
            t8 = fmaxf(t8, __shfl_xor_sync(0xffffffffu, t8, o));
        }
        const float mn0 = fmaxf(m0, t0), mn8 = fmaxf(m8, t8);
        const float al0 = __expf(m0 - mn0), al8 = __expf(m8 - mn8);
        m0 = mn0; m8 = mn8;
        float rs0 = 0.f, rs8 = 0.f;
        #pragma unroll
        for (int nt = 0; nt < 8; nt++) {
            sc[nt][0] = __expf(sc[nt][0] - mn0); rs0 += sc[nt][0];
            sc[nt][1] = __expf(sc[nt][1] - mn0); rs0 += sc[nt][1];
            sc[nt][2] = __expf(sc[nt][2] - mn8); rs8 += sc[nt][2];
            sc[nt][3] = __expf(sc[nt][3] - mn8); rs8 += sc[nt][3];
        }
        #pragma unroll
        for (int o = 1; o <= 2; o <<= 1) {
            rs0 += __shfl_xor_sync(0xffffffffu, rs0, o);
            rs8 += __shfl_xor_sync(0xffffffffu, rs8, o);
        }
        l0 = l0 * al0 + rs0;
        l8 = l8 * al8 + rs8;
        #pragma unroll
        for (int nt = 0; nt < 8; nt++) {
            of[nt][0] *= al0; of[nt][1] *= al0;
            of[nt][2] *= al8; of[nt][3] *= al8;
        }

        #pragma unroll
        for (int ks = 0; ks < 4; ks++) {
            uint32_t ap[4];
            __half2 h0 = __floats2half2_rn(sc[2 * ks][0],     sc[2 * ks][1]);
            __half2 h1 = __floats2half2_rn(sc[2 * ks][2],     sc[2 * ks][3]);
            __half2 h2 = __floats2half2_rn(sc[2 * ks + 1][0], sc[2 * ks + 1][1]);
            __half2 h3 = __floats2half2_rn(sc[2 * ks + 1][2], sc[2 * ks + 1][3]);
            ap[0] = *(uint32_t*)&h0; ap[1] = *(uint32_t*)&h1;
            ap[2] = *(uint32_t*)&h2; ap[3] = *(uint32_t*)&h3;
            uint32_t vb[4][4];
            const int kk = ks * 16 + lr;
            #pragma unroll
            for (int nv = 0; nv < 4; nv++) {
                const uint32_t cn = ((uint32_t)(2 * nv + lc)) ^ (kk & 7);
                ldm_x4_t(vb[nv], vsB + (uint32_t)(kk * 128) + (cn << 4));
            }
            #pragma unroll
            for (int nt = 0; nt < 8; nt++)
                mma_f16(of[nt], ap, &vb[nt >> 1][(nt & 1) * 2]);
        }
    }

    const float rl0 = 1.f / l0, rl8 = 1.f / l8;
    const int rowA = bb * 2048 + q0 + wid * 16 + r0;
    #pragma unroll
    for (int nt = 0; nt < 8; nt++) {
        const int c = h * 64 + nt * 8 + (lane & 3) * 2;
        *(__half2*)&g_ctx[(size_t)rowA * 1024 + c] =
            __floats2half2_rn(of[nt][0] * rl0, of[nt][1] * rl0);
        *(__half2*)&g_ctx[(size_t)(rowA + 8) * 1024 + c] =
            __floats2half2_rn(of[nt][2] * rl8, of[nt][3] * rl8);
    }
}

// ---------------- launch ----------------
extern "C" void kernel_launch(void* const* d_in, const int* in_sizes, int n_in,
                              void* d_out, int out_size)
{
    (void)in_sizes; (void)n_in; (void)out_size;
    const float* x      = (const float*)d_in[0];
    const float* respos = (const float*)d_in[1];
    const float* w_qkv  = (const float*)d_in[2];
    const float* b_qkv  = (const float*)d_in[3];
    const float* w_out  = (const float*)d_in[4];
    const float* b_out  = (const float*)d_in[5];
    const float* w1     = (const float*)d_in[6];
    const float* b1     = (const float*)d_in[7];
    const float* w2     = (const float*)d_in[8];
    const float* b2     = (const float*)d_in[9];
    const float* ln1_g  = (const float*)d_in[10];
    const float* ln1_b  = (const float*)d_in[11];
    const float* ln2_g  = (const float*)d_in[12];
    const float* ln2_b  = (const float*)d_in[13];
    float* out = (float*)d_out;

    cudaFuncSetAttribute(gemm_mma<false, false, true >, cudaFuncAttributeMaxDynamicSharedMemorySize, GEMM_DSM);
    cudaFuncSetAttribute(gemm_mma<false, true,  false>, cudaFuncAttributeMaxDynamicSharedMemorySize, GEMM_DSM);
    cudaFuncSetAttribute(gemm_mma<true,  false, true >, cudaFuncAttributeMaxDynamicSharedMemorySize, GEMM_DSM);

    // 1. merged weight cast
    cast_all_kernel<<<12288, 256>>>(w_qkv, w_out, w1, w2);
    // 2. ln1 -> g_ln (fp16)
    ln_h_kernel<<<MROWS, 256>>>(x, 0, ln1_g, ln1_b);
    // 3. qkv = ln1 @ wqkv + b_qkv -> g_qkvh (fp16)
    gemm_mma<false, false, true><<<dim3(24, 32), 256, GEMM_DSM>>>(
        3072, 1024, 1, 3, b_qkv, nullptr, 0, nullptr, 8);
    // 4. HMMA attention -> g_ctx (fp16)
    attn_kernel<<<dim3(16, 16, 2), 256>>>(respos);
    // 5. x1 = x + ctx @ wout + b_out -> g_x1 (fp32)   [ncu capture slot ~#6]
    gemm_mma<false, true, false><<<dim3(8, 32), 256, GEMM_DSM>>>(
        1024, 1024, 2, 4, b_out, x, 0, nullptr, 2);
    // 6. ln2 -> g_ln
    ln_h_kernel<<<MROWS, 256>>>(nullptr, 2, ln2_g, ln2_b);
    // 7. ffn1 = relu(ln2 @ w1 + b1) -> g_ffn1 (fp16)
    gemm_mma<true, false, true><<<dim3(32, 32), 256, GEMM_DSM>>>(
        4096, 1024, 1, 5, b1, nullptr, 0, nullptr, 7);
    // 8. out = x1 + ffn1 @ w2 + b2 -> d_out (fp32)
    gemm_mma<false, true, false><<<dim3(8, 32), 256, GEMM_DSM>>>(
        1024, 4096, 7, 6, b2, nullptr, 2, out, 0);
}

// round 13
// speedup vs baseline: 1.4110x; 1.0400x over previous
#include <cuda_runtime.h>
#include <cuda_fp16.h>
#include <stdint.h>
#include <math.h>

#define MROWS 4096

// ---------------- scratch (fp16 operands) ----------------
__device__ __half g_ln  [(size_t)MROWS * 1024];
__device__ __half g_ctx [(size_t)MROWS * 1024];
__device__ __half g_wqkv[(size_t)1024 * 3072];
__device__ __half g_wout[(size_t)1024 * 1024];
__device__ __half g_w1  [(size_t)1024 * 4096];
__device__ __half g_w2  [(size_t)4096 * 1024];
__device__ __half g_ffn1[(size_t)MROWS * 4096];
__device__ __half g_qkvh[(size_t)MROWS * 3072];
__device__ float  g_x1  [(size_t)MROWS * 1024];

__device__ __forceinline__ const __half* bufh(int c)
{
    switch (c) {
        case 1: return g_ln;
        case 2: return g_ctx;
        case 3: return g_wqkv;
        case 4: return g_wout;
        case 5: return g_w1;
        case 6: return g_w2;
        case 7: return g_ffn1;
        default: return g_qkvh;
    }
}
__device__ __forceinline__ float* buff(int c, const float* p)
{
    switch (c) {
        case 2: return g_x1;
        default: return (float*)p;
    }
}

// ---------------- PTX helpers (baseline PTX; safe on plain sm_103) ----------
__device__ __forceinline__ uint32_t smem_u32(const void* p)
{
    uint32_t a;
    asm("{ .reg .u64 t; cvta.to.shared.u64 t, %1; cvt.u32.u64 %0, t; }" : "=r"(a) : "l"(p));
    return a;
}
__device__ __forceinline__ void ldm_x4(uint32_t* r, uint32_t a)
{
    asm volatile("ldmatrix.sync.aligned.m8n8.x4.shared.b16 {%0,%1,%2,%3}, [%4];"
        : "=r"(r[0]), "=r"(r[1]), "=r"(r[2]), "=r"(r[3]) : "r"(a));
}
__device__ __forceinline__ void ldm_x4_t(uint32_t* r, uint32_t a)
{
    asm volatile("ldmatrix.sync.aligned.m8n8.x4.trans.shared.b16 {%0,%1,%2,%3}, [%4];"
        : "=r"(r[0]), "=r"(r[1]), "=r"(r[2]), "=r"(r[3]) : "r"(a));
}
__device__ __forceinline__ void mma_f16(float* c, const uint32_t* a, const uint32_t* b)
{
    asm volatile("mma.sync.aligned.m16n8k16.row.col.f32.f16.f16.f32 "
        "{%0,%1,%2,%3}, {%4,%5,%6,%7}, {%8,%9}, {%0,%1,%2,%3};"
        : "+f"(c[0]), "+f"(c[1]), "+f"(c[2]), "+f"(c[3])
        : "r"(a[0]), "r"(a[1]), "r"(a[2]), "r"(a[3]), "r"(b[0]), "r"(b[1]));
}
__device__ __forceinline__ void cpa16(uint32_t s, const void* g)
{
    asm volatile("cp.async.cg.shared.global [%0], [%1], 16;" :: "r"(s), "l"(g));
}
#define CPA_COMMIT() asm volatile("cp.async.commit_group;" ::: "memory")
#define CPA_WAIT(n)  asm volatile("cp.async.wait_group %0;" :: "n"(n) : "memory")

// ---------------- single merged weight cast: f32 -> f16 ----------------
__global__ __launch_bounds__(256) void cast_all_kernel(const float* __restrict__ wqkv,
                                                       const float* __restrict__ wout,
                                                       const float* __restrict__ w1,
                                                       const float* __restrict__ w2)
{
    const int bid = blockIdx.x;
    const float* src;
    __half* dst;
    int lb;
    if (bid < 3072)      { src = wqkv; dst = g_wqkv; lb = bid; }
    else if (bid < 4096) { src = wout; dst = g_wout; lb = bid - 3072; }
    else if (bid < 8192) { src = w1;   dst = g_w1;   lb = bid - 4096; }
    else                 { src = w2;   dst = g_w2;   lb = bid - 8192; }
    const size_t i = (size_t)lb * 256 + threadIdx.x;
    const float4 v = reinterpret_cast<const float4*>(src)[i];
    *(__half2*)&dst[i * 4]     = __floats2half2_rn(v.x, v.y);
    *(__half2*)&dst[i * 4 + 2] = __floats2half2_rn(v.z, v.w);
}

// ---------------- LayerNorm -> fp16 [row, 1024] ----------------
__global__ __launch_bounds__(256) void ln_h_kernel(const float* __restrict__ xp, int xc,
                                                   const float* __restrict__ gam,
                                                   const float* __restrict__ bet)
{
    const float* x = buff(xc, xp);
    __shared__ float sh[8];
    __shared__ float stat[2];
    const int row = blockIdx.x, t = threadIdx.x;

    const float4 v = reinterpret_cast<const float4*>(x)[(size_t)row * 256 + t];
    float s = v.x + v.y + v.z + v.w;
    #pragma unroll
    for (int o = 16; o; o >>= 1) s += __shfl_xor_sync(0xffffffffu, s, o);
    if ((t & 31) == 0) sh[t >> 5] = s;
    __syncthreads();
    if (t < 32) {
        float u = (t < 8) ? sh[t] : 0.f;
        #pragma unroll
        for (int o = 4; o; o >>= 1) u += __shfl_xor_sync(0xffffffffu, u, o);
        if (t == 0) stat[0] = u * (1.f / 1024.f);
    }
    __syncthreads();
    const float mu = stat[0];
    const float a = v.x - mu, b = v.y - mu, c = v.z - mu, d = v.w - mu;
    float s2 = a * a + b * b + c * c + d * d;
    #pragma unroll
    for (int o = 16; o; o >>= 1) s2 += __shfl_xor_sync(0xffffffffu, s2, o);
    if ((t & 31) == 0) sh[t >> 5] = s2;
    __syncthreads();
    if (t < 32) {
        float u = (t < 8) ? sh[t] : 0.f;
        #pragma unroll
        for (int o = 4; o; o >>= 1) u += __shfl_xor_sync(0xffffffffu, u, o);
        if (t == 0) stat[1] = rsqrtf(u * (1.f / 1024.f) + 1e-5f);
    }
    __syncthreads();
    const float inv = stat[1];
    const float4 gv = *(const float4*)(gam + t * 4);
    const float4 bv = *(const float4*)(bet + t * 4);
    const float o0 = a * inv * gv.x + bv.x, o1 = b * inv * gv.y + bv.y;
    const float o2 = c * inv * gv.z + bv.z, o3 = d * inv * gv.w + bv.w;
    const size_t base = (size_t)row * 1024 + t * 4;
    *(__half2*)&g_ln[base]     = __floats2half2_rn(o0, o1);
    *(__half2*)&g_ln[base + 2] = __floats2half2_rn(o2, o3);
}

// ---------------- HMMA fp16 GEMM (cp.async 4-stage BK=32, 64KB dynamic) ------
#define GEMM_DSM (4 * 16384)

template<bool RELU, bool RESID, bool HALFOUT>
__global__ __launch_bounds__(256, 2) void gemm_mma(
    int N, int KTOT, int Ac, int Bc,
    const float* __restrict__ bias,
    const float* resp, int resc,
    float* Cp, int Cc)
{
    const __half* A  = bufh(Ac);
    const __half* Bw = bufh(Bc);
    const float* res = buff(resc, resp);
    float* C = HALFOUT ? nullptr : buff(Cc, Cp);
    __half* Ch = HALFOUT ? (__half*)bufh(Cc) : nullptr;

    extern __shared__ __align__(16) char dsm[];

    const int tid = threadIdx.x;
    const int wid = tid >> 5, lane = tid & 31;
    const int wm = wid & 3, wn = wid >> 2;
    const int brow = blockIdx.y, bcol = blockIdx.x;

    const __half* Ablk = A + (size_t)(brow * 128) * KTOT;
    const __half* Bblk = Bw + bcol * 128;

    const uint32_t smB = smem_u32(dsm);

    const int ar = tid >> 2, acn = tid & 3;
    const int bk = tid >> 4, bcn = tid & 15;
    const uint32_t aso0 = (uint32_t)(ar * 64  + ((acn ^ ((ar >> 1) & 3)) << 4));
    const uint32_t aso1 = (uint32_t)((ar + 64) * 64 + ((acn ^ (((ar + 64) >> 1) & 3)) << 4));
    const uint32_t bso0 = (uint32_t)(8192 + bk * 256 + ((bcn ^ (bk & 7)) << 4));
    const uint32_t bso1 = (uint32_t)(8192 + (bk + 16) * 256 + ((bcn ^ ((bk + 16) & 7)) << 4));

    const int lr = lane & 15, lc = lane >> 4;
    const int arow[2] = { wm * 32 + lr, wm * 32 + 16 + lr };
    const uint32_t aswz[2] = { (uint32_t)((arow[0] >> 1) & 3), (uint32_t)((arow[1] >> 1) & 3) };
    const uint32_t bswzk = (uint32_t)(lr & 7);

    float acc[2][8][4];
    #pragma unroll
    for (int mt = 0; mt < 2; mt++)
        #pragma unroll
        for (int nt = 0; nt < 8; nt++)
            #pragma unroll
            for (int q = 0; q < 4; q++) acc[mt][nt][q] = 0.f;

    const int NS = KTOT >> 5;

    auto issue = [&](int ss) {
        const int kg = ss * 32;
        const uint32_t st = smB + (uint32_t)((ss & 3) * 16384);
        cpa16(st + aso0, Ablk + (size_t)ar * KTOT + kg + acn * 8);
        cpa16(st + aso1, Ablk + (size_t)(ar + 64) * KTOT + kg + acn * 8);
        cpa16(st + bso0, Bblk + (size_t)(kg + bk) * N + bcn * 8);
        cpa16(st + bso1, Bblk + (size_t)(kg + bk + 16) * N + bcn * 8);
        CPA_COMMIT();
    };

    issue(0);
    issue(1);
    issue(2);

    #pragma unroll 1
    for (int s = 0; s < NS; s++) {
        if (s + 2 < NS) { CPA_WAIT(2); } else { CPA_WAIT(0); }
        __syncthreads();
        if (s + 3 < NS) issue(s + 3);

        const uint32_t aB = smB + (uint32_t)((s & 3) * 16384);
        const uint32_t bB = aB + 8192;
        #pragma unroll
        for (int ks = 0; ks < 2; ks++) {
            uint32_t af[2][4], bf[4][4];
            #pragma unroll
            for (int mt = 0; mt < 2; mt++) {
                const uint32_t chunk = ((uint32_t)(ks * 2 + lc)) ^ aswz[mt];
                ldm_x4(af[mt], aB + (uint32_t)(arow[mt] * 64) + (chunk << 4));
            }
            const uint32_t kk = (uint32_t)(ks * 16 + lr);
            #pragma unroll
            for (int n16 = 0; n16 < 4; n16++) {
                const uint32_t cn = ((uint32_t)(wn * 8 + n16 * 2 + lc)) ^ bswzk;
                ldm_x4_t(bf[n16], bB + kk * 256 + (cn << 4));
            }
            #pragma unroll
            for (int mt = 0; mt < 2; mt++)
                #pragma unroll
                for (int nt = 0; nt < 8; nt++)
                    mma_f16(acc[mt][nt], af[mt], &bf[nt >> 1][(nt & 1) * 2]);
        }
    }

    const int rbase = brow * 128 + wm * 32 + (lane >> 2);
    const int cbase = bcol * 128 + wn * 64 + (lane & 3) * 2;
    #pragma unroll
    for (int mt = 0; mt < 2; mt++) {
        #pragma unroll
        for (int nt = 0; nt < 8; nt++) {
            const int c = cbase + nt * 8;
            const float2 bv = *(const float2*)(bias + c);
            #pragma unroll
            for (int hrow = 0; hrow < 2; hrow++) {
                const int r = rbase + mt * 16 + hrow * 8;
                float v0 = acc[mt][nt][hrow * 2]     + bv.x;
                float v1 = acc[mt][nt][hrow * 2 + 1] + bv.y;
                if (HALFOUT) {
                    if (RELU) { v0 = fmaxf(v0, 0.f); v1 = fmaxf(v1, 0.f); }
                    *(__half2*)&Ch[(size_t)r * N + c] = __floats2half2_rn(v0, v1);
                } else {
                    const size_t off = (size_t)r * N + c;
                    if (RESID) {
                        const float2 rv = *(const float2*)(res + off);
                        v0 += rv.x; v1 += rv.y;
                    }
                    float2 ov; ov.x = v0; ov.y = v1;
                    *(float2*)(C + off) = ov;
                }
            }
        }
    }
}

// ---------------- HMMA windowed flash attention (cp.async dbl-buf K/V) -------
// Dynamic smem 48KB: Qs[128x64] (16KB) + 2 stages of (K 8KB + V 8KB).
// __launch_bounds__(256,2): regs<=128 -> 2 CTA/SM.
#define ATT_DSM (16384 + 2 * 16384)

__global__ __launch_bounds__(256, 2) void attn_kernel(const float* __restrict__ res_pos)
{
    extern __shared__ __align__(16) char adsm[];
    __shared__ float rp[512];

    const __half* qkv = g_qkvh;
    const int bx = blockIdx.x, h = blockIdx.y, bb = blockIdx.z;
    const int q0 = bx * 128;
    const int tid = threadIdx.x, wid = tid >> 5, lane = tid & 31;
    const int lr = lane & 15, lc = lane >> 4;
    const int r0 = lane >> 2;

    const uint32_t base = smem_u32(adsm);
    const uint32_t qsB = base;

    for (int i = tid; i < 512; i += 256) rp[i] = res_pos[h * 512 + i];

    // cp.async K/V tile issue into stage b: K at +0, V at +8192
    const int kvr = (tid & 127) >> 1;              // 0..63 row within tile half
    // per-thread coords for 4 chunks: idx = i*256+tid; arr=idx>>9; rem=idx&511
    auto issue_kv = [&](int kt, int b) {
        const uint32_t st = base + 16384 + (uint32_t)(b * 16384);
        #pragma unroll
        for (int i = 0; i < 4; i++) {
            const int idx = i * 256 + tid;
            const int arr = idx >> 9, rem = idx & 511;
            const int r = rem >> 3, c = rem & 7;
            cpa16(st + (uint32_t)(arr * 8192 + r * 128 + (((uint32_t)c ^ (r & 7)) << 4)),
                  qkv + (size_t)(bb * 2048 + kt * 64 + r) * 3072 + 1024 + arr * 1024
                      + h * 64 + c * 8);
        }
        CPA_COMMIT();
    };
    (void)kvr;

    const int ktlo = (q0 >= 511) ? ((q0 - 511) >> 6) : 0;
    const int kthi = (q0 + 127) >> 6;

    issue_kv(ktlo, 0);

    // load Q tile (plain stores; overlaps with in-flight K/V cp.async)
    #pragma unroll
    for (int i = 0; i < 4; i++) {
        const int idx = i * 256 + tid;
        const int r = idx >> 3, c = idx & 7;
        *(uint4*)(adsm + r * 128 + (((uint32_t)c ^ (r & 7)) << 4)) =
            *(const uint4*)(qkv + (size_t)(bb * 2048 + q0 + r) * 3072 + h * 64 + c * 8);
    }
    __syncthreads();

    uint32_t qf[4][4];
    #pragma unroll
    for (int ks = 0; ks < 4; ks++) {
        const int row = wid * 16 + lr;
        const uint32_t chunk = ((uint32_t)(2 * ks + lc)) ^ (row & 7);
        ldm_x4(qf[ks], qsB + (uint32_t)(row * 128) + (chunk << 4));
    }

    float m0 = -1e30f, m8 = -1e30f, l0 = 0.f, l8 = 0.f;
    float of[8][4];
    #pragma unroll
    for (int nt = 0; nt < 8; nt++)
        #pragma unroll
        for (int q = 0; q < 4; q++) of[nt][q] = 0.f;

    for (int kt = ktlo; kt <= kthi; kt++) {
        const int s = kt - ktlo;
        CPA_WAIT(0);
        __syncthreads();                        // stage s&1 visible; prior reads done
        if (kt + 1 <= kthi) issue_kv(kt + 1, (s + 1) & 1);

        const uint32_t ksB = base + 16384 + (uint32_t)((s & 1) * 16384);
        const uint32_t vsB = ksB + 8192;

        float sc[8][4];
        #pragma unroll
        for (int nt = 0; nt < 8; nt++)
            #pragma unroll
            for (int q = 0; q < 4; q++) sc[nt][q] = 0.f;
        #pragma unroll
        for (int cd = 0; cd < 4; cd++) {
            uint32_t kb[4][4];
            #pragma unroll
            for (int g = 0; g < 4; g++) {
                const int kr = g * 16 + lr;
                const uint32_t chunk = ((uint32_t)(2 * cd + lc)) ^ (kr & 7);
                ldm_x4(kb[g], ksB + (uint32_t)(kr * 128) + (chunk << 4));
            }
            #pragma unroll
            for (int nt = 0; nt < 8; nt++) {
                uint32_t bp[2];
                const int g = nt >> 1;
                if (nt & 1) { bp[0] = kb[g][1]; bp[1] = kb[g][3]; }
                else        { bp[0] = kb[g][0]; bp[1] = kb[g][2]; }
                mma_f16(sc[nt], qf[cd], bp);
            }
        }

        const int qr = q0 + wid * 16 + r0;
        #pragma unroll
        for (int nt = 0; nt < 8; nt++) {
            const int key0 = kt * 64 + nt * 8 + (lane & 3) * 2;
            #pragma unroll
            for (int j = 0; j < 2; j++) {
                const int dd  = qr - (key0 + j);
                const int dd8 = dd + 8;
                sc[nt][j]     = (dd  >= 0 && dd  < 512) ? sc[nt][j]     * 0.125f + rp[dd]  : -1e30f;
                sc[nt][2 + j] = (dd8 >= 0 && dd8 < 512) ? sc[nt][2 + j] * 0.125f + rp[dd8] : -1e30f;
            }
        }

        float t0 = -1e30f, t8 = -1e30f;
        #pragma unroll
        for (int nt = 0; nt < 8; nt++) {
            t0 = fmaxf(t0, fmaxf(sc[nt][0], sc[nt][1]));
            t8 = fmaxf(t8, fmaxf(sc[nt][2], sc[nt][3]));
        }
        #pragma unroll
        for (int o = 1; o <= 2; o <<= 1) {
            t0 = fmaxf(t0, __shfl_xor_sync(0xffffffffu, t0, o));
            t8 = fmaxf(t8, __shfl_xor_sync(0xffffffffu, t8, o));
        }
        const float mn0 = fmaxf(m0, t0), mn8 = fmaxf(m8, t8);
        const float al0 = __expf(m0 - mn0), al8 = __expf(m8 - mn8);
        m0 = mn0; m8 = mn8;
        float rs0 = 0.f, rs8 = 0.f;
        #pragma unroll
        for (int nt = 0; nt < 8; nt++) {
            sc[nt][0] = __expf(sc[nt][0] - mn0); rs0 += sc[nt][0];
            sc[nt][1] = __expf(sc[nt][1] - mn0); rs0 += sc[nt][1];
            sc[nt][2] = __expf(sc[nt][2] - mn8); rs8 += sc[nt][2];
            sc[nt][3] = __expf(sc[nt][3] - mn8); rs8 += sc[nt][3];
        }
        #pragma unroll
        for (int o = 1; o <= 2; o <<= 1) {
            rs0 += __shfl_xor_sync(0xffffffffu, rs0, o);
            rs8 += __shfl_xor_sync(0xffffffffu, rs8, o);
        }
        l0 = l0 * al0 + rs0;
        l8 = l8 * al8 + rs8;
        #pragma unroll
        for (int nt = 0; nt < 8; nt++) {
            of[nt][0] *= al0; of[nt][1] *= al0;
            of[nt][2] *= al8; of[nt][3] *= al8;
        }

        #pragma unroll
        for (int ks = 0; ks < 4; ks++) {
            uint32_t ap[4];
            __half2 h0 = __floats2half2_rn(sc[2 * ks][0],     sc[2 * ks][1]);
            __half2 h1 = __floats2half2_rn(sc[2 * ks][2],     sc[2 * ks][3]);
            __half2 h2 = __floats2half2_rn(sc[2 * ks + 1][0], sc[2 * ks + 1][1]);
            __half2 h3 = __floats2half2_rn(sc[2 * ks + 1][2], sc[2 * ks + 1][3]);
            ap[0] = *(uint32_t*)&h0; ap[1] = *(uint32_t*)&h1;
            ap[2] = *(uint32_t*)&h2; ap[3] = *(uint32_t*)&h3;
            uint32_t vb[4][4];
            const int kk = ks * 16 + lr;
            #pragma unroll
            for (int nv = 0; nv < 4; nv++) {
                const uint32_t cn = ((uint32_t)(2 * nv + lc)) ^ (kk & 7);
                ldm_x4_t(vb[nv], vsB + (uint32_t)(kk * 128) + (cn << 4));
            }
            #pragma unroll
            for (int nt = 0; nt < 8; nt++)
                mma_f16(of[nt], ap, &vb[nt >> 1][(nt & 1) * 2]);
        }
    }

    const float rl0 = 1.f / l0, rl8 = 1.f / l8;
    const int rowA = bb * 2048 + q0 + wid * 16 + r0;
    #pragma unroll
    for (int nt = 0; nt < 8; nt++) {
        const int c = h * 64 + nt * 8 + (lane & 3) * 2;
        *(__half2*)&g_ctx[(size_t)rowA * 1024 + c] =
            __floats2half2_rn(of[nt][0] * rl0, of[nt][1] * rl0);
        *(__half2*)&g_ctx[(size_t)(rowA + 8) * 1024 + c] =
            __floats2half2_rn(of[nt][2] * rl8, of[nt][3] * rl8);
    }
}

// ---------------- launch ----------------
extern "C" void kernel_launch(void* const* d_in, const int* in_sizes, int n_in,
                              void* d_out, int out_size)
{
    (void)in_sizes; (void)n_in; (void)out_size;
    const float* x      = (const float*)d_in[0];
    const float* respos = (const float*)d_in[1];
    const float* w_qkv  = (const float*)d_in[2];
    const float* b_qkv  = (const float*)d_in[3];
    const float* w_out  = (const float*)d_in[4];
    const float* b_out  = (const float*)d_in[5];
    const float* w1     = (const float*)d_in[6];
    const float* b1     = (const float*)d_in[7];
    const float* w2     = (const float*)d_in[8];
    const float* b2     = (const float*)d_in[9];
    const float* ln1_g  = (const float*)d_in[10];
    const float* ln1_b  = (const float*)d_in[11];
    const float* ln2_g  = (const float*)d_in[12];
    const float* ln2_b  = (const float*)d_in[13];
    float* out = (float*)d_out;

    cudaFuncSetAttribute(gemm_mma<false, false, true >, cudaFuncAttributeMaxDynamicSharedMemorySize, GEMM_DSM);
    cudaFuncSetAttribute(gemm_mma<false, true,  false>, cudaFuncAttributeMaxDynamicSharedMemorySize, GEMM_DSM);
    cudaFuncSetAttribute(gemm_mma<true,  false, true >, cudaFuncAttributeMaxDynamicSharedMemorySize, GEMM_DSM);
    cudaFuncSetAttribute(attn_kernel, cudaFuncAttributeMaxDynamicSharedMemorySize, ATT_DSM);

    // 1. merged weight cast
    cast_all_kernel<<<12288, 256>>>(w_qkv, w_out, w1, w2);
    // 2. ln1 -> g_ln (fp16)
    ln_h_kernel<<<MROWS, 256>>>(x, 0, ln1_g, ln1_b);
    // 3. qkv = ln1 @ wqkv + b_qkv -> g_qkvh (fp16)
    gemm_mma<false, false, true><<<dim3(24, 32), 256, GEMM_DSM>>>(
        3072, 1024, 1, 3, b_qkv, nullptr, 0, nullptr, 8);
    // 4. HMMA attention -> g_ctx (fp16)
    attn_kernel<<<dim3(16, 16, 2), 256, ATT_DSM>>>(respos);
    // 5. x1 = x + ctx @ wout + b_out -> g_x1 (fp32)
    gemm_mma<false, true, false><<<dim3(8, 32), 256, GEMM_DSM>>>(
        1024, 1024, 2, 4, b_out, x, 0, nullptr, 2);
    // 6. ln2 -> g_ln
    ln_h_kernel<<<MROWS, 256>>>(nullptr, 2, ln2_g, ln2_b);
    // 7. ffn1 = relu(ln2 @ w1 + b1) -> g_ffn1 (fp16)
    gemm_mma<true, false, true><<<dim3(32, 32), 256, GEMM_DSM>>>(
        4096, 1024, 1, 5, b1, nullptr, 0, nullptr, 7);
    // 8. out = x1 + ffn1 @ w2 + b2 -> d_out (fp32)
    gemm_mma<false, true, false><<<dim3(8, 32), 256, GEMM_DSM>>>(
        1024, 4096, 7, 6, b2, nullptr, 2, out, 0);
}

// round 14
// speedup vs baseline: 1.4501x; 1.0277x over previous
#include <cuda_runtime.h>
#include <cuda_fp16.h>
#include <stdint.h>
#include <math.h>

#define MROWS 4096

// ---------------- scratch (fp16 operands) ----------------
__device__ __half g_ln  [(size_t)MROWS * 1024];
__device__ __half g_ctx [(size_t)MROWS * 1024];
__device__ __half g_wqkv[(size_t)1024 * 3072];
__device__ __half g_wout[(size_t)1024 * 1024];
__device__ __half g_w1  [(size_t)1024 * 4096];
__device__ __half g_w2  [(size_t)4096 * 1024];
__device__ __half g_ffn1[(size_t)MROWS * 4096];
__device__ __half g_qkvh[(size_t)MROWS * 3072];
__device__ float  g_x1  [(size_t)MROWS * 1024];

__device__ __forceinline__ const __half* bufh(int c)
{
    switch (c) {
        case 1: return g_ln;
        case 2: return g_ctx;
        case 3: return g_wqkv;
        case 4: return g_wout;
        case 5: return g_w1;
        case 6: return g_w2;
        case 7: return g_ffn1;
        default: return g_qkvh;
    }
}
__device__ __forceinline__ float* buff(int c, const float* p)
{
    switch (c) {
        case 2: return g_x1;
        default: return (float*)p;
    }
}

// ---------------- PTX helpers (baseline PTX; safe on plain sm_103) ----------
__device__ __forceinline__ uint32_t smem_u32(const void* p)
{
    uint32_t a;
    asm("{ .reg .u64 t; cvta.to.shared.u64 t, %1; cvt.u32.u64 %0, t; }" : "=r"(a) : "l"(p));
    return a;
}
__device__ __forceinline__ void ldm_x4(uint32_t* r, uint32_t a)
{
    asm volatile("ldmatrix.sync.aligned.m8n8.x4.shared.b16 {%0,%1,%2,%3}, [%4];"
        : "=r"(r[0]), "=r"(r[1]), "=r"(r[2]), "=r"(r[3]) : "r"(a));
}
__device__ __forceinline__ void ldm_x4_t(uint32_t* r, uint32_t a)
{
    asm volatile("ldmatrix.sync.aligned.m8n8.x4.trans.shared.b16 {%0,%1,%2,%3}, [%4];"
        : "=r"(r[0]), "=r"(r[1]), "=r"(r[2]), "=r"(r[3]) : "r"(a));
}
__device__ __forceinline__ void mma_f16(float* c, const uint32_t* a, const uint32_t* b)
{
    asm volatile("mma.sync.aligned.m16n8k16.row.col.f32.f16.f16.f32 "
        "{%0,%1,%2,%3}, {%4,%5,%6,%7}, {%8,%9}, {%0,%1,%2,%3};"
        : "+f"(c[0]), "+f"(c[1]), "+f"(c[2]), "+f"(c[3])
        : "r"(a[0]), "r"(a[1]), "r"(a[2]), "r"(a[3]), "r"(b[0]), "r"(b[1]));
}
__device__ __forceinline__ void cpa16(uint32_t s, const void* g)
{
    asm volatile("cp.async.cg.shared.global [%0], [%1], 16;" :: "r"(s), "l"(g));
}
#define CPA_COMMIT() asm volatile("cp.async.commit_group;" ::: "memory")
#define CPA_WAIT(n)  asm volatile("cp.async.wait_group %0;" :: "n"(n) : "memory")

// ---------------- merged weight cast, MLP=4: f32 -> f16 ----------------
// 3072 blocks x 256 thr; each thread converts 4 independent float4s.
__global__ __launch_bounds__(256) void cast_all_kernel(const float* __restrict__ wqkv,
                                                       const float* __restrict__ wout,
                                                       const float* __restrict__ w1,
                                                       const float* __restrict__ w2)
{
    const int bid = blockIdx.x;
    const float* src;
    __half* dst;
    int lb;
    if (bid < 768)       { src = wqkv; dst = g_wqkv; lb = bid; }
    else if (bid < 1024) { src = wout; dst = g_wout; lb = bid - 768; }
    else if (bid < 2048) { src = w1;   dst = g_w1;   lb = bid - 1024; }
    else                 { src = w2;   dst = g_w2;   lb = bid - 2048; }
    const size_t base = (size_t)lb * 1024 + threadIdx.x;
    float4 v[4];
    #pragma unroll
    for (int k = 0; k < 4; k++)
        v[k] = reinterpret_cast<const float4*>(src)[base + k * 256];
    #pragma unroll
    for (int k = 0; k < 4; k++) {
        const size_t e = (base + k * 256) * 4;
        *(__half2*)&dst[e]     = __floats2half2_rn(v[k].x, v[k].y);
        *(__half2*)&dst[e + 2] = __floats2half2_rn(v[k].z, v[k].w);
    }
}

// ---------------- LayerNorm -> fp16 [row, 1024] ----------------
__global__ __launch_bounds__(256) void ln_h_kernel(const float* __restrict__ xp, int xc,
                                                   const float* __restrict__ gam,
                                                   const float* __restrict__ bet)
{
    const float* x = buff(xc, xp);
    __shared__ float sh[8];
    __shared__ float stat[2];
    const int row = blockIdx.x, t = threadIdx.x;

    const float4 v = reinterpret_cast<const float4*>(x)[(size_t)row * 256 + t];
    float s = v.x + v.y + v.z + v.w;
    #pragma unroll
    for (int o = 16; o; o >>= 1) s += __shfl_xor_sync(0xffffffffu, s, o);
    if ((t & 31) == 0) sh[t >> 5] = s;
    __syncthreads();
    if (t < 32) {
        float u = (t < 8) ? sh[t] : 0.f;
        #pragma unroll
        for (int o = 4; o; o >>= 1) u += __shfl_xor_sync(0xffffffffu, u, o);
        if (t == 0) stat[0] = u * (1.f / 1024.f);
    }
    __syncthreads();
    const float mu = stat[0];
    const float a = v.x - mu, b = v.y - mu, c = v.z - mu, d = v.w - mu;
    float s2 = a * a + b * b + c * c + d * d;
    #pragma unroll
    for (int o = 16; o; o >>= 1) s2 += __shfl_xor_sync(0xffffffffu, s2, o);
    if ((t & 31) == 0) sh[t >> 5] = s2;
    __syncthreads();
    if (t < 32) {
        float u = (t < 8) ? sh[t] : 0.f;
        #pragma unroll
        for (int o = 4; o; o >>= 1) u += __shfl_xor_sync(0xffffffffu, u, o);
        if (t == 0) stat[1] = rsqrtf(u * (1.f / 1024.f) + 1e-5f);
    }
    __syncthreads();
    const float inv = stat[1];
    const float4 gv = *(const float4*)(gam + t * 4);
    const float4 bv = *(const float4*)(bet + t * 4);
    const float o0 = a * inv * gv.x + bv.x, o1 = b * inv * gv.y + bv.y;
    const float o2 = c * inv * gv.z + bv.z, o3 = d * inv * gv.w + bv.w;
    const size_t base = (size_t)row * 1024 + t * 4;
    *(__half2*)&g_ln[base]     = __floats2half2_rn(o0, o1);
    *(__half2*)&g_ln[base + 2] = __floats2half2_rn(o2, o3);
}

// ---------------- HMMA fp16 GEMM (cp.async 4-stage BK=32, 64KB dynamic) ------
#define GEMM_DSM (4 * 16384)

template<bool RELU, bool RESID, bool HALFOUT>
__global__ __launch_bounds__(256, 2) void gemm_mma(
    int N, int KTOT, int Ac, int Bc,
    const float* __restrict__ bias,
    const float* resp, int resc,
    float* Cp, int Cc)
{
    const __half* A  = bufh(Ac);
    const __half* Bw = bufh(Bc);
    const float* res = buff(resc, resp);
    float* C = HALFOUT ? nullptr : buff(Cc, Cp);
    __half* Ch = HALFOUT ? (__half*)bufh(Cc) : nullptr;

    extern __shared__ __align__(16) char dsm[];

    const int tid = threadIdx.x;
    const int wid = tid >> 5, lane = tid & 31;
    const int wm = wid & 3, wn = wid >> 2;
    const int brow = blockIdx.y, bcol = blockIdx.x;

    const __half* Ablk = A + (size_t)(brow * 128) * KTOT;
    const __half* Bblk = Bw + bcol * 128;

    const uint32_t smB = smem_u32(dsm);

    const int ar = tid >> 2, acn = tid & 3;
    const int bk = tid >> 4, bcn = tid & 15;
    const uint32_t aso0 = (uint32_t)(ar * 64  + ((acn ^ ((ar >> 1) & 3)) << 4));
    const uint32_t aso1 = (uint32_t)((ar + 64) * 64 + ((acn ^ (((ar + 64) >> 1) & 3)) << 4));
    const uint32_t bso0 = (uint32_t)(8192 + bk * 256 + ((bcn ^ (bk & 7)) << 4));
    const uint32_t bso1 = (uint32_t)(8192 + (bk + 16) * 256 + ((bcn ^ ((bk + 16) & 7)) << 4));

    const int lr = lane & 15, lc = lane >> 4;
    const int arow[2] = { wm * 32 + lr, wm * 32 + 16 + lr };
    const uint32_t aswz[2] = { (uint32_t)((arow[0] >> 1) & 3), (uint32_t)((arow[1] >> 1) & 3) };
    const uint32_t bswzk = (uint32_t)(lr & 7);

    float acc[2][8][4];
    #pragma unroll
    for (int mt = 0; mt < 2; mt++)
        #pragma unroll
        for (int nt = 0; nt < 8; nt++)
            #pragma unroll
            for (int q = 0; q < 4; q++) acc[mt][nt][q] = 0.f;

    const int NS = KTOT >> 5;

    auto issue = [&](int ss) {
        const int kg = ss * 32;
        const uint32_t st = smB + (uint32_t)((ss & 3) * 16384);
        cpa16(st + aso0, Ablk + (size_t)ar * KTOT + kg + acn * 8);
        cpa16(st + aso1, Ablk + (size_t)(ar + 64) * KTOT + kg + acn * 8);
        cpa16(st + bso0, Bblk + (size_t)(kg + bk) * N + bcn * 8);
        cpa16(st + bso1, Bblk + (size_t)(kg + bk + 16) * N + bcn * 8);
        CPA_COMMIT();
    };

    issue(0);
    issue(1);
    issue(2);

    #pragma unroll 1
    for (int s = 0; s < NS; s++) {
        if (s + 2 < NS) { CPA_WAIT(2); } else { CPA_WAIT(0); }
        __syncthreads();
        if (s + 3 < NS) issue(s + 3);

        const uint32_t aB = smB + (uint32_t)((s & 3) * 16384);
        const uint32_t bB = aB + 8192;
        #pragma unroll
        for (int ks = 0; ks < 2; ks++) {
            uint32_t af[2][4], bf[4][4];
            #pragma unroll
            for (int mt = 0; mt < 2; mt++) {
                const uint32_t chunk = ((uint32_t)(ks * 2 + lc)) ^ aswz[mt];
                ldm_x4(af[mt], aB + (uint32_t)(arow[mt] * 64) + (chunk << 4));
            }
            const uint32_t kk = (uint32_t)(ks * 16 + lr);
            #pragma unroll
            for (int n16 = 0; n16 < 4; n16++) {
                const uint32_t cn = ((uint32_t)(wn * 8 + n16 * 2 + lc)) ^ bswzk;
                ldm_x4_t(bf[n16], bB + kk * 256 + (cn << 4));
            }
            #pragma unroll
            for (int mt = 0; mt < 2; mt++)
                #pragma unroll
                for (int nt = 0; nt < 8; nt++)
                    mma_f16(acc[mt][nt], af[mt], &bf[nt >> 1][(nt & 1) * 2]);
        }
    }

    const int rbase = brow * 128 + wm * 32 + (lane >> 2);
    const int cbase = bcol * 128 + wn * 64 + (lane & 3) * 2;
    #pragma unroll
    for (int mt = 0; mt < 2; mt++) {
        #pragma unroll
        for (int nt = 0; nt < 8; nt++) {
            const int c = cbase + nt * 8;
            const float2 bv = *(const float2*)(bias + c);
            #pragma unroll
            for (int hrow = 0; hrow < 2; hrow++) {
                const int r = rbase + mt * 16 + hrow * 8;
                float v0 = acc[mt][nt][hrow * 2]     + bv.x;
                float v1 = acc[mt][nt][hrow * 2 + 1] + bv.y;
                if (HALFOUT) {
                    if (RELU) { v0 = fmaxf(v0, 0.f); v1 = fmaxf(v1, 0.f); }
                    *(__half2*)&Ch[(size_t)r * N + c] = __floats2half2_rn(v0, v1);
                } else {
                    const size_t off = (size_t)r * N + c;
                    if (RESID) {
                        const float2 rv = *(const float2*)(res + off);
                        v0 += rv.x; v1 += rv.y;
                    }
                    float2 ov; ov.x = v0; ov.y = v1;
                    *(float2*)(C + off) = ov;
                }
            }
        }
    }
}

// ---------------- HMMA windowed flash attention, constant-shift softmax ------
// p = exp(0.125*s + rpx[dd]) with rpx = bias - 4 (or -1e30 outside window).
// No online max, no rescaling; l reduced once after the k-loop.
#define ATT_DSM (16384 + 2 * 16384)

__global__ __launch_bounds__(256, 2) void attn_kernel(const float* __restrict__ res_pos)
{
    extern __shared__ __align__(16) char adsm[];
    __shared__ float rpx[896];   // dd in [-192, 704)

    const __half* qkv = g_qkvh;
    const int bx = blockIdx.x, h = blockIdx.y, bb = blockIdx.z;
    const int q0 = bx * 128;
    const int tid = threadIdx.x, wid = tid >> 5, lane = tid & 31;
    const int lr = lane & 15, lc = lane >> 4;
    const int r0 = lane >> 2;

    const uint32_t base = smem_u32(adsm);
    const uint32_t qsB = base;

    for (int i = tid; i < 896; i += 256) {
        const int dd = i - 192;
        rpx[i] = (dd >= 0 && dd < 512) ? res_pos[h * 512 + dd] - 4.0f : -1e30f;
    }

    auto issue_kv = [&](int kt, int b) {
        const uint32_t st = base + 16384 + (uint32_t)(b * 16384);
        #pragma unroll
        for (int i = 0; i < 4; i++) {
            const int idx = i * 256 + tid;
            const int arr = idx >> 9, rem = idx & 511;
            const int r = rem >> 3, c = rem & 7;
            cpa16(st + (uint32_t)(arr * 8192 + r * 128 + (((uint32_t)c ^ (r & 7)) << 4)),
                  qkv + (size_t)(bb * 2048 + kt * 64 + r) * 3072 + 1024 + arr * 1024
                      + h * 64 + c * 8);
        }
        CPA_COMMIT();
    };

    const int ktlo = (q0 >= 511) ? ((q0 - 511) >> 6) : 0;
    const int kthi = (q0 + 127) >> 6;

    issue_kv(ktlo, 0);

    #pragma unroll
    for (int i = 0; i < 4; i++) {
        const int idx = i * 256 + tid;
        const int r = idx >> 3, c = idx & 7;
        *(uint4*)(adsm + r * 128 + (((uint32_t)c ^ (r & 7)) << 4)) =
            *(const uint4*)(qkv + (size_t)(bb * 2048 + q0 + r) * 3072 + h * 64 + c * 8);
    }
    __syncthreads();

    uint32_t qf[4][4];
    #pragma unroll
    for (int ks = 0; ks < 4; ks++) {
        const int row = wid * 16 + lr;
        const uint32_t chunk = ((uint32_t)(2 * ks + lc)) ^ (row & 7);
        ldm_x4(qf[ks], qsB + (uint32_t)(row * 128) + (chunk << 4));
    }

    float l0 = 0.f, l8 = 0.f;
    float of[8][4];
    #pragma unroll
    for (int nt = 0; nt < 8; nt++)
        #pragma unroll
        for (int q = 0; q < 4; q++) of[nt][q] = 0.f;

    const int qr = q0 + wid * 16 + r0;

    for (int kt = ktlo; kt <= kthi; kt++) {
        const int s = kt - ktlo;
        CPA_WAIT(0);
        __syncthreads();
        if (kt + 1 <= kthi) issue_kv(kt + 1, (s + 1) & 1);

        const uint32_t ksB = base + 16384 + (uint32_t)((s & 1) * 16384);
        const uint32_t vsB = ksB + 8192;

        float sc[8][4];
        #pragma unroll
        for (int nt = 0; nt < 8; nt++)
            #pragma unroll
            for (int q = 0; q < 4; q++) sc[nt][q] = 0.f;
        #pragma unroll
        for (int cd = 0; cd < 4; cd++) {
            uint32_t kb[4][4];
            #pragma unroll
            for (int g = 0; g < 4; g++) {
                const int kr = g * 16 + lr;
                const uint32_t chunk = ((uint32_t)(2 * cd + lc)) ^ (kr & 7);
                ldm_x4(kb[g], ksB + (uint32_t)(kr * 128) + (chunk << 4));
            }
            #pragma unroll
            for (int nt = 0; nt < 8; nt++) {
                uint32_t bp[2];
                const int g = nt >> 1;
                if (nt & 1) { bp[0] = kb[g][1]; bp[1] = kb[g][3]; }
                else        { bp[0] = kb[g][0]; bp[1] = kb[g][2]; }
                mma_f16(sc[nt], qf[cd], bp);
            }
        }

        // constant-shift softmax weights: p = exp(0.125*s + rpx[dd])
        const int tb = qr - kt * 64 - (lane & 3) * 2 + 192;
        #pragma unroll
        for (int nt = 0; nt < 8; nt++) {
            const int ti = tb - nt * 8;
            const float p0 = __expf(fmaf(sc[nt][0], 0.125f, rpx[ti]));
            const float p1 = __expf(fmaf(sc[nt][1], 0.125f, rpx[ti - 1]));
            const float p2 = __expf(fmaf(sc[nt][2], 0.125f, rpx[ti + 8]));
            const float p3 = __expf(fmaf(sc[nt][3], 0.125f, rpx[ti + 7]));
            sc[nt][0] = p0; sc[nt][1] = p1; sc[nt][2] = p2; sc[nt][3] = p3;
            l0 += p0 + p1;
            l8 += p2 + p3;
        }

        // O += P V
        #pragma unroll
        for (int ks = 0; ks < 4; ks++) {
            uint32_t ap[4];
            __half2 h0 = __floats2half2_rn(sc[2 * ks][0],     sc[2 * ks][1]);
            __half2 h1 = __floats2half2_rn(sc[2 * ks][2],     sc[2 * ks][3]);
            __half2 h2 = __floats2half2_rn(sc[2 * ks + 1][0], sc[2 * ks + 1][1]);
            __half2 h3 = __floats2half2_rn(sc[2 * ks + 1][2], sc[2 * ks + 1][3]);
            ap[0] = *(uint32_t*)&h0; ap[1] = *(uint32_t*)&h1;
            ap[2] = *(uint32_t*)&h2; ap[3] = *(uint32_t*)&h3;
            uint32_t vb[4][4];
            const int kk = ks * 16 + lr;
            #pragma unroll
            for (int nv = 0; nv < 4; nv++) {
                const uint32_t cn = ((uint32_t)(2 * nv + lc)) ^ (kk & 7);
                ldm_x4_t(vb[nv], vsB + (uint32_t)(kk * 128) + (cn << 4));
            }
            #pragma unroll
            for (int nt = 0; nt < 8; nt++)
                mma_f16(of[nt], ap, &vb[nt >> 1][(nt & 1) * 2]);
        }
    }

    // single final l reduction across the 4 lanes of each row-quad
    #pragma unroll
    for (int o = 1; o <= 2; o <<= 1) {
        l0 += __shfl_xor_sync(0xffffffffu, l0, o);
        l8 += __shfl_xor_sync(0xffffffffu, l8, o);
    }
    const float rl0 = 1.f / l0, rl8 = 1.f / l8;
    const int rowA = bb * 2048 + q0 + wid * 16 + r0;
    #pragma unroll
    for (int nt = 0; nt < 8; nt++) {
        const int c = h * 64 + nt * 8 + (lane & 3) * 2;
        *(__half2*)&g_ctx[(size_t)rowA * 1024 + c] =
            __floats2half2_rn(of[nt][0] * rl0, of[nt][1] * rl0);
        *(__half2*)&g_ctx[(size_t)(rowA + 8) * 1024 + c] =
            __floats2half2_rn(of[nt][2] * rl8, of[nt][3] * rl8);
    }
}

// ---------------- launch ----------------
extern "C" void kernel_launch(void* const* d_in, const int* in_sizes, int n_in,
                              void* d_out, int out_size)
{
    (void)in_sizes; (void)n_in; (void)out_size;
    const float* x      = (const float*)d_in[0];
    const float* respos = (const float*)d_in[1];
    const float* w_qkv  = (const float*)d_in[2];
    const float* b_qkv  = (const float*)d_in[3];
    const float* w_out  = (const float*)d_in[4];
    const float* b_out  = (const float*)d_in[5];
    const float* w1     = (const float*)d_in[6];
    const float* b1     = (const float*)d_in[7];
    const float* w2     = (const float*)d_in[8];
    const float* b2     = (const float*)d_in[9];
    const float* ln1_g  = (const float*)d_in[10];
    const float* ln1_b  = (const float*)d_in[11];
    const float* ln2_g  = (const float*)d_in[12];
    const float* ln2_b  = (const float*)d_in[13];
    float* out = (float*)d_out;

    cudaFuncSetAttribute(gemm_mma<false, false, true >, cudaFuncAttributeMaxDynamicSharedMemorySize, GEMM_DSM);
    cudaFuncSetAttribute(gemm_mma<false, true,  false>, cudaFuncAttributeMaxDynamicSharedMemorySize, GEMM_DSM);
    cudaFuncSetAttribute(gemm_mma<true,  false, true >, cudaFuncAttributeMaxDynamicSharedMemorySize, GEMM_DSM);
    cudaFuncSetAttribute(attn_kernel, cudaFuncAttributeMaxDynamicSharedMemorySize, ATT_DSM);

    // 1. merged weight cast (MLP=4)
    cast_all_kernel<<<3072, 256>>>(w_qkv, w_out, w1, w2);
    // 2. ln1 -> g_ln (fp16)
    ln_h_kernel<<<MROWS, 256>>>(x, 0, ln1_g, ln1_b);
    // 3. qkv = ln1 @ wqkv + b_qkv -> g_qkvh (fp16)
    gemm_mma<false, false, true><<<dim3(24, 32), 256, GEMM_DSM>>>(
        3072, 1024, 1, 3, b_qkv, nullptr, 0, nullptr, 8);
    // 4. HMMA attention -> g_ctx (fp16)
    attn_kernel<<<dim3(16, 16, 2), 256, ATT_DSM>>>(respos);
    // 5. x1 = x + ctx @ wout + b_out -> g_x1 (fp32)
    gemm_mma<false, true, false><<<dim3(8, 32), 256, GEMM_DSM>>>(
        1024, 1024, 2, 4, b_out, x, 0, nullptr, 2);
    // 6. ln2 -> g_ln
    ln_h_kernel<<<MROWS, 256>>>(nullptr, 2, ln2_g, ln2_b);
    // 7. ffn1 = relu(ln2 @ w1 + b1) -> g_ffn1 (fp16)
    gemm_mma<true, false, true><<<dim3(32, 32), 256, GEMM_DSM>>>(
        4096, 1024, 1, 5, b1, nullptr, 0, nullptr, 7);
    // 8. out = x1 + ffn1 @ w2 + b2 -> d_out (fp32)
    gemm_mma<false, true, false><<<dim3(8, 32), 256, GEMM_DSM>>>(
        1024, 4096, 7, 6, b2, nullptr, 2, out, 0);
}

// round 15
// speedup vs baseline: 1.4912x; 1.0283x over previous
#include <cuda_runtime.h>
#include <cuda_fp16.h>
#include <stdint.h>
#include <math.h>

#define MROWS 4096

// ---------------- scratch (fp16 operands) ----------------
__device__ __half g_ln  [(size_t)MROWS * 1024];
__device__ __half g_ctx [(size_t)MROWS * 1024];
__device__ __half g_wqkv[(size_t)1024 * 3072];
__device__ __half g_wout[(size_t)1024 * 1024];
__device__ __half g_w1  [(size_t)1024 * 4096];
__device__ __half g_w2  [(size_t)4096 * 1024];
__device__ __half g_ffn1[(size_t)MROWS * 4096];
__device__ __half g_qkvh[(size_t)MROWS * 3072];
__device__ float  g_x1  [(size_t)MROWS * 1024];

__device__ __forceinline__ const __half* bufh(int c)
{
    switch (c) {
        case 1: return g_ln;
        case 2: return g_ctx;
        case 3: return g_wqkv;
        case 4: return g_wout;
        case 5: return g_w1;
        case 6: return g_w2;
        case 7: return g_ffn1;
        default: return g_qkvh;
    }
}
__device__ __forceinline__ float* buff(int c, const float* p)
{
    switch (c) {
        case 2: return g_x1;
        default: return (float*)p;
    }
}

// ---------------- PTX helpers (baseline PTX; safe on plain sm_103) ----------
__device__ __forceinline__ uint32_t smem_u32(const void* p)
{
    uint32_t a;
    asm("{ .reg .u64 t; cvta.to.shared.u64 t, %1; cvt.u32.u64 %0, t; }" : "=r"(a) : "l"(p));
    return a;
}
__device__ __forceinline__ void ldm_x4(uint32_t* r, uint32_t a)
{
    asm volatile("ldmatrix.sync.aligned.m8n8.x4.shared.b16 {%0,%1,%2,%3}, [%4];"
        : "=r"(r[0]), "=r"(r[1]), "=r"(r[2]), "=r"(r[3]) : "r"(a));
}
__device__ __forceinline__ void ldm_x4_t(uint32_t* r, uint32_t a)
{
    asm volatile("ldmatrix.sync.aligned.m8n8.x4.trans.shared.b16 {%0,%1,%2,%3}, [%4];"
        : "=r"(r[0]), "=r"(r[1]), "=r"(r[2]), "=r"(r[3]) : "r"(a));
}
__device__ __forceinline__ void mma_f16(float* c, const uint32_t* a, const uint32_t* b)
{
    asm volatile("mma.sync.aligned.m16n8k16.row.col.f32.f16.f16.f32 "
        "{%0,%1,%2,%3}, {%4,%5,%6,%7}, {%8,%9}, {%0,%1,%2,%3};"
        : "+f"(c[0]), "+f"(c[1]), "+f"(c[2]), "+f"(c[3])
        : "r"(a[0]), "r"(a[1]), "r"(a[2]), "r"(a[3]), "r"(b[0]), "r"(b[1]));
}
__device__ __forceinline__ void cpa16(uint32_t s, const void* g)
{
    asm volatile("cp.async.cg.shared.global [%0], [%1], 16;" :: "r"(s), "l"(g));
}
#define CPA_COMMIT() asm volatile("cp.async.commit_group;" ::: "memory")
#define CPA_WAIT(n)  asm volatile("cp.async.wait_group %0;" :: "n"(n) : "memory")

// ---------------- merged cast (MLP=4) + ln1 kernel ----------------
// bid < 3072: weight cast; bid >= 3072: ln1 row (bid - 3072).
__global__ __launch_bounds__(256) void cast_ln1_kernel(
    const float* __restrict__ wqkv, const float* __restrict__ wout,
    const float* __restrict__ w1,   const float* __restrict__ w2,
    const float* __restrict__ x,
    const float* __restrict__ gam,  const float* __restrict__ bet)
{
    __shared__ float sh[8];
    __shared__ float stat[2];
    const int bid = blockIdx.x, t = threadIdx.x;

    if (bid < 3072) {
        const float* src;
        __half* dst;
        int lb;
        if (bid < 768)       { src = wqkv; dst = g_wqkv; lb = bid; }
        else if (bid < 1024) { src = wout; dst = g_wout; lb = bid - 768; }
        else if (bid < 2048) { src = w1;   dst = g_w1;   lb = bid - 1024; }
        else                 { src = w2;   dst = g_w2;   lb = bid - 2048; }
        const size_t base = (size_t)lb * 1024 + t;
        float4 v[4];
        #pragma unroll
        for (int k = 0; k < 4; k++)
            v[k] = reinterpret_cast<const float4*>(src)[base + k * 256];
        #pragma unroll
        for (int k = 0; k < 4; k++) {
            const size_t e = (base + k * 256) * 4;
            *(__half2*)&dst[e]     = __floats2half2_rn(v[k].x, v[k].y);
            *(__half2*)&dst[e + 2] = __floats2half2_rn(v[k].z, v[k].w);
        }
        return;
    }

    const int row = bid - 3072;
    const float4 v = reinterpret_cast<const float4*>(x)[(size_t)row * 256 + t];
    float s = v.x + v.y + v.z + v.w;
    #pragma unroll
    for (int o = 16; o; o >>= 1) s += __shfl_xor_sync(0xffffffffu, s, o);
    if ((t & 31) == 0) sh[t >> 5] = s;
    __syncthreads();
    if (t < 32) {
        float u = (t < 8) ? sh[t] : 0.f;
        #pragma unroll
        for (int o = 4; o; o >>= 1) u += __shfl_xor_sync(0xffffffffu, u, o);
        if (t == 0) stat[0] = u * (1.f / 1024.f);
    }
    __syncthreads();
    const float mu = stat[0];
    const float a = v.x - mu, b = v.y - mu, c = v.z - mu, d = v.w - mu;
    float s2 = a * a + b * b + c * c + d * d;
    #pragma unroll
    for (int o = 16; o; o >>= 1) s2 += __shfl_xor_sync(0xffffffffu, s2, o);
    if ((t & 31) == 0) sh[t >> 5] = s2;
    __syncthreads();
    if (t < 32) {
        float u = (t < 8) ? sh[t] : 0.f;
        #pragma unroll
        for (int o = 4; o; o >>= 1) u += __shfl_xor_sync(0xffffffffu, u, o);
        if (t == 0) stat[1] = rsqrtf(u * (1.f / 1024.f) + 1e-5f);
    }
    __syncthreads();
    const float inv = stat[1];
    const float4 gv = *(const float4*)(gam + t * 4);
    const float4 bv = *(const float4*)(bet + t * 4);
    const float o0 = a * inv * gv.x + bv.x, o1 = b * inv * gv.y + bv.y;
    const float o2 = c * inv * gv.z + bv.z, o3 = d * inv * gv.w + bv.w;
    const size_t base = (size_t)row * 1024 + t * 4;
    *(__half2*)&g_ln[base]     = __floats2half2_rn(o0, o1);
    *(__half2*)&g_ln[base + 2] = __floats2half2_rn(o2, o3);
}

// ---------------- LayerNorm -> fp16 (ln2 path) ----------------
__global__ __launch_bounds__(256) void ln_h_kernel(const float* __restrict__ xp, int xc,
                                                   const float* __restrict__ gam,
                                                   const float* __restrict__ bet)
{
    const float* x = buff(xc, xp);
    __shared__ float sh[8];
    __shared__ float stat[2];
    const int row = blockIdx.x, t = threadIdx.x;

    const float4 v = reinterpret_cast<const float4*>(x)[(size_t)row * 256 + t];
    float s = v.x + v.y + v.z + v.w;
    #pragma unroll
    for (int o = 16; o; o >>= 1) s += __shfl_xor_sync(0xffffffffu, s, o);
    if ((t & 31) == 0) sh[t >> 5] = s;
    __syncthreads();
    if (t < 32) {
        float u = (t < 8) ? sh[t] : 0.f;
        #pragma unroll
        for (int o = 4; o; o >>= 1) u += __shfl_xor_sync(0xffffffffu, u, o);
        if (t == 0) stat[0] = u * (1.f / 1024.f);
    }
    __syncthreads();
    const float mu = stat[0];
    const float a = v.x - mu, b = v.y - mu, c = v.z - mu, d = v.w - mu;
    float s2 = a * a + b * b + c * c + d * d;
    #pragma unroll
    for (int o = 16; o; o >>= 1) s2 += __shfl_xor_sync(0xffffffffu, s2, o);
    if ((t & 31) == 0) sh[t >> 5] = s2;
    __syncthreads();
    if (t < 32) {
        float u = (t < 8) ? sh[t] : 0.f;
        #pragma unroll
        for (int o = 4; o; o >>= 1) u += __shfl_xor_sync(0xffffffffu, u, o);
        if (t == 0) stat[1] = rsqrtf(u * (1.f / 1024.f) + 1e-5f);
    }
    __syncthreads();
    const float inv = stat[1];
    const float4 gv = *(const float4*)(gam + t * 4);
    const float4 bv = *(const float4*)(bet + t * 4);
    const float o0 = a * inv * gv.x + bv.x, o1 = b * inv * gv.y + bv.y;
    const float o2 = c * inv * gv.z + bv.z, o3 = d * inv * gv.w + bv.w;
    const size_t base = (size_t)row * 1024 + t * 4;
    *(__half2*)&g_ln[base]     = __floats2half2_rn(o0, o1);
    *(__half2*)&g_ln[base + 2] = __floats2half2_rn(o2, o3);
}

// ---------------- HMMA fp16 GEMM: 6-stage ring, 2 stages per sync ------------
// CTA 128x128, 256 thr, 8 warps (4m x 2n). Stage = A[128x32] + B[32x128] = 16KB.
// 6 stages (96KB dynamic); consume 2 stages per barrier -> 16 syncs for K=1024.
#define GEMM_DSM (6 * 16384)

template<bool RELU, bool RESID, bool HALFOUT>
__global__ __launch_bounds__(256, 2) void gemm_mma(
    int N, int KTOT, int Ac, int Bc,
    const float* __restrict__ bias,
    const float* resp, int resc,
    float* Cp, int Cc)
{
    const __half* A  = bufh(Ac);
    const __half* Bw = bufh(Bc);
    const float* res = buff(resc, resp);
    float* C = HALFOUT ? nullptr : buff(Cc, Cp);
    __half* Ch = HALFOUT ? (__half*)bufh(Cc) : nullptr;

    extern __shared__ __align__(16) char dsm[];

    const int tid = threadIdx.x;
    const int wid = tid >> 5, lane = tid & 31;
    const int wm = wid & 3, wn = wid >> 2;
    const int brow = blockIdx.y, bcol = blockIdx.x;

    const __half* Ablk = A + (size_t)(brow * 128) * KTOT;
    const __half* Bblk = Bw + bcol * 128;

    const uint32_t smB = smem_u32(dsm);

    const int ar = tid >> 2, acn = tid & 3;
    const int bk = tid >> 4, bcn = tid & 15;
    const uint32_t aso0 = (uint32_t)(ar * 64  + ((acn ^ ((ar >> 1) & 3)) << 4));
    const uint32_t aso1 = (uint32_t)((ar + 64) * 64 + ((acn ^ (((ar + 64) >> 1) & 3)) << 4));
    const uint32_t bso0 = (uint32_t)(8192 + bk * 256 + ((bcn ^ (bk & 7)) << 4));
    const uint32_t bso1 = (uint32_t)(8192 + (bk + 16) * 256 + ((bcn ^ ((bk + 16) & 7)) << 4));

    const int lr = lane & 15, lc = lane >> 4;
    const int arow[2] = { wm * 32 + lr, wm * 32 + 16 + lr };
    const uint32_t aswz[2] = { (uint32_t)((arow[0] >> 1) & 3), (uint32_t)((arow[1] >> 1) & 3) };
    const uint32_t bswzk = (uint32_t)(lr & 7);

    float acc[2][8][4];
    #pragma unroll
    for (int mt = 0; mt < 2; mt++)
        #pragma unroll
        for (int nt = 0; nt < 8; nt++)
            #pragma unroll
            for (int q = 0; q < 4; q++) acc[mt][nt][q] = 0.f;

    const int NS = KTOT >> 5;   // always even (32 or 128)

    auto issue = [&](int ss) {
        const int kg = ss * 32;
        const uint32_t st = smB + (uint32_t)((ss % 6) * 16384);
        cpa16(st + aso0, Ablk + (size_t)ar * KTOT + kg + acn * 8);
        cpa16(st + aso1, Ablk + (size_t)(ar + 64) * KTOT + kg + acn * 8);
        cpa16(st + bso0, Bblk + (size_t)(kg + bk) * N + bcn * 8);
        cpa16(st + bso1, Bblk + (size_t)(kg + bk + 16) * N + bcn * 8);
        CPA_COMMIT();
    };

    issue(0); issue(1); issue(2); issue(3);

    #pragma unroll 1
    for (int s = 0; s < NS; s += 2) {
        if (s + 2 < NS) { CPA_WAIT(2); } else { CPA_WAIT(0); }
        __syncthreads();                    // stages s,s+1 visible; old reads retired
        if (s + 4 < NS) issue(s + 4);
        if (s + 5 < NS) issue(s + 5);

        #pragma unroll
        for (int half = 0; half < 2; half++) {
            const uint32_t aB = smB + (uint32_t)(((s + half) % 6) * 16384);
            const uint32_t bB = aB + 8192;
            #pragma unroll
            for (int ks = 0; ks < 2; ks++) {
                uint32_t af[2][4], bf[4][4];
                #pragma unroll
                for (int mt = 0; mt < 2; mt++) {
                    const uint32_t chunk = ((uint32_t)(ks * 2 + lc)) ^ aswz[mt];
                    ldm_x4(af[mt], aB + (uint32_t)(arow[mt] * 64) + (chunk << 4));
                }
                const uint32_t kk = (uint32_t)(ks * 16 + lr);
                #pragma unroll
                for (int n16 = 0; n16 < 4; n16++) {
                    const uint32_t cn = ((uint32_t)(wn * 8 + n16 * 2 + lc)) ^ bswzk;
                    ldm_x4_t(bf[n16], bB + kk * 256 + (cn << 4));
                }
                #pragma unroll
                for (int mt = 0; mt < 2; mt++)
                    #pragma unroll
                    for (int nt = 0; nt < 8; nt++)
                        mma_f16(acc[mt][nt], af[mt], &bf[nt >> 1][(nt & 1) * 2]);
            }
        }
    }

    const int rbase = brow * 128 + wm * 32 + (lane >> 2);
    const int cbase = bcol * 128 + wn * 64 + (lane & 3) * 2;
    #pragma unroll
    for (int mt = 0; mt < 2; mt++) {
        #pragma unroll
        for (int nt = 0; nt < 8; nt++) {
            const int c = cbase + nt * 8;
            const float2 bv = *(const float2*)(bias + c);
            #pragma unroll
            for (int hrow = 0; hrow < 2; hrow++) {
                const int r = rbase + mt * 16 + hrow * 8;
                float v0 = acc[mt][nt][hrow * 2]     + bv.x;
                float v1 = acc[mt][nt][hrow * 2 + 1] + bv.y;
                if (HALFOUT) {
                    if (RELU) { v0 = fmaxf(v0, 0.f); v1 = fmaxf(v1, 0.f); }
                    *(__half2*)&Ch[(size_t)r * N + c] = __floats2half2_rn(v0, v1);
                } else {
                    const size_t off = (size_t)r * N + c;
                    if (RESID) {
                        const float2 rv = *(const float2*)(res + off);
                        v0 += rv.x; v1 += rv.y;
                    }
                    float2 ov; ov.x = v0; ov.y = v1;
                    *(float2*)(C + off) = ov;
                }
            }
        }
    }
}

// ---------------- HMMA windowed flash attention, constant-shift softmax ------
#define ATT_DSM (16384 + 2 * 16384)

__global__ __launch_bounds__(256, 2) void attn_kernel(const float* __restrict__ res_pos)
{
    extern __shared__ __align__(16) char adsm[];
    __shared__ float rpx[896];   // dd in [-192, 704)

    const __half* qkv = g_qkvh;
    const int bx = blockIdx.x, h = blockIdx.y, bb = blockIdx.z;
    const int q0 = bx * 128;
    const int tid = threadIdx.x, wid = tid >> 5, lane = tid & 31;
    const int lr = lane & 15, lc = lane >> 4;
    const int r0 = lane >> 2;

    const uint32_t base = smem_u32(adsm);
    const uint32_t qsB = base;

    for (int i = tid; i < 896; i += 256) {
        const int dd = i - 192;
        rpx[i] = (dd >= 0 && dd < 512) ? res_pos[h * 512 + dd] - 4.0f : -1e30f;
    }

    auto issue_kv = [&](int kt, int b) {
        const uint32_t st = base + 16384 + (uint32_t)(b * 16384);
        #pragma unroll
        for (int i = 0; i < 4; i++) {
            const int idx = i * 256 + tid;
            const int arr = idx >> 9, rem = idx & 511;
            const int r = rem >> 3, c = rem & 7;
            cpa16(st + (uint32_t)(arr * 8192 + r * 128 + (((uint32_t)c ^ (r & 7)) << 4)),
                  qkv + (size_t)(bb * 2048 + kt * 64 + r) * 3072 + 1024 + arr * 1024
                      + h * 64 + c * 8);
        }
        CPA_COMMIT();
    };

    const int ktlo = (q0 >= 511) ? ((q0 - 511) >> 6) : 0;
    const int kthi = (q0 + 127) >> 6;

    issue_kv(ktlo, 0);

    #pragma unroll
    for (int i = 0; i < 4; i++) {
        const int idx = i * 256 + tid;
        const int r = idx >> 3, c = idx & 7;
        *(uint4*)(adsm + r * 128 + (((uint32_t)c ^ (r & 7)) << 4)) =
            *(const uint4*)(qkv + (size_t)(bb * 2048 + q0 + r) * 3072 + h * 64 + c * 8);
    }
    __syncthreads();

    uint32_t qf[4][4];
    #pragma unroll
    for (int ks = 0; ks < 4; ks++) {
        const int row = wid * 16 + lr;
        const uint32_t chunk = ((uint32_t)(2 * ks + lc)) ^ (row & 7);
        ldm_x4(qf[ks], qsB + (uint32_t)(row * 128) + (chunk << 4));
    }

    float l0 = 0.f, l8 = 0.f;
    float of[8][4];
    #pragma unroll
    for (int nt = 0; nt < 8; nt++)
        #pragma unroll
        for (int q = 0; q < 4; q++) of[nt][q] = 0.f;

    const int qr = q0 + wid * 16 + r0;

    for (int kt = ktlo; kt <= kthi; kt++) {
        const int s = kt - ktlo;
        CPA_WAIT(0);
        __syncthreads();
        if (kt + 1 <= kthi) issue_kv(kt + 1, (s + 1) & 1);

        const uint32_t ksB = base + 16384 + (uint32_t)((s & 1) * 16384);
        const uint32_t vsB = ksB + 8192;

        float sc[8][4];
        #pragma unroll
        for (int nt = 0; nt < 8; nt++)
            #pragma unroll
            for (int q = 0; q < 4; q++) sc[nt][q] = 0.f;
        #pragma unroll
        for (int cd = 0; cd < 4; cd++) {
            uint32_t kb[4][4];
            #pragma unroll
            for (int g = 0; g < 4; g++) {
                const int kr = g * 16 + lr;
                const uint32_t chunk = ((uint32_t)(2 * cd + lc)) ^ (kr & 7);
                ldm_x4(kb[g], ksB + (uint32_t)(kr * 128) + (chunk << 4));
            }
            #pragma unroll
            for (int nt = 0; nt < 8; nt++) {
                uint32_t bp[2];
                const int g = nt >> 1;
                if (nt & 1) { bp[0] = kb[g][1]; bp[1] = kb[g][3]; }
                else        { bp[0] = kb[g][0]; bp[1] = kb[g][2]; }
                mma_f16(sc[nt], qf[cd], bp);
            }
        }

        const int tb = qr - kt * 64 - (lane & 3) * 2 + 192;
        #pragma unroll
        for (int nt = 0; nt < 8; nt++) {
            const int ti = tb - nt * 8;
            const float p0 = __expf(fmaf(sc[nt][0], 0.125f, rpx[ti]));
            const float p1 = __expf(fmaf(sc[nt][1], 0.125f, rpx[ti - 1]));
            const float p2 = __expf(fmaf(sc[nt][2], 0.125f, rpx[ti + 8]));
            const float p3 = __expf(fmaf(sc[nt][3], 0.125f, rpx[ti + 7]));
            sc[nt][0] = p0; sc[nt][1] = p1; sc[nt][2] = p2; sc[nt][3] = p3;
            l0 += p0 + p1;
            l8 += p2 + p3;
        }

        #pragma unroll
        for (int ks = 0; ks < 4; ks++) {
            uint32_t ap[4];
            __half2 h0 = __floats2half2_rn(sc[2 * ks][0],     sc[2 * ks][1]);
            __half2 h1 = __floats2half2_rn(sc[2 * ks][2],     sc[2 * ks][3]);
            __half2 h2 = __floats2half2_rn(sc[2 * ks + 1][0], sc[2 * ks + 1][1]);
            __half2 h3 = __floats2half2_rn(sc[2 * ks + 1][2], sc[2 * ks + 1][3]);
            ap[0] = *(uint32_t*)&h0; ap[1] = *(uint32_t*)&h1;
            ap[2] = *(uint32_t*)&h2; ap[3] = *(uint32_t*)&h3;
            uint32_t vb[4][4];
            const int kk = ks * 16 + lr;
            #pragma unroll
            for (int nv = 0; nv < 4; nv++) {
                const uint32_t cn = ((uint32_t)(2 * nv + lc)) ^ (kk & 7);
                ldm_x4_t(vb[nv], vsB + (uint32_t)(kk * 128) + (cn << 4));
            }
            #pragma unroll
            for (int nt = 0; nt < 8; nt++)
                mma_f16(of[nt], ap, &vb[nt >> 1][(nt & 1) * 2]);
        }
    }

    #pragma unroll
    for (int o = 1; o <= 2; o <<= 1) {
        l0 += __shfl_xor_sync(0xffffffffu, l0, o);
        l8 += __shfl_xor_sync(0xffffffffu, l8, o);
    }
    const float rl0 = 1.f / l0, rl8 = 1.f / l8;
    const int rowA = bb * 2048 + q0 + wid * 16 + r0;
    #pragma unroll
    for (int nt = 0; nt < 8; nt++) {
        const int c = h * 64 + nt * 8 + (lane & 3) * 2;
        *(__half2*)&g_ctx[(size_t)rowA * 1024 + c] =
            __floats2half2_rn(of[nt][0] * rl0, of[nt][1] * rl0);
        *(__half2*)&g_ctx[(size_t)(rowA + 8) * 1024 + c] =
            __floats2half2_rn(of[nt][2] * rl8, of[nt][3] * rl8);
    }
}

// ---------------- launch ----------------
extern "C" void kernel_launch(void* const* d_in, const int* in_sizes, int n_in,
                              void* d_out, int out_size)
{
    (void)in_sizes; (void)n_in; (void)out_size;
    const float* x      = (const float*)d_in[0];
    const float* respos = (const float*)d_in[1];
    const float* w_qkv  = (const float*)d_in[2];
    const float* b_qkv  = (const float*)d_in[3];
    const float* w_out  = (const float*)d_in[4];
    const float* b_out  = (const float*)d_in[5];
    const float* w1     = (const float*)d_in[6];
    const float* b1     = (const float*)d_in[7];
    const float* w2     = (const float*)d_in[8];
    const float* b2     = (const float*)d_in[9];
    const float* ln1_g  = (const float*)d_in[10];
    const float* ln1_b  = (const float*)d_in[11];
    const float* ln2_g  = (const float*)d_in[12];
    const float* ln2_b  = (const float*)d_in[13];
    float* out = (float*)d_out;

    cudaFuncSetAttribute(gemm_mma<false, false, true >, cudaFuncAttributeMaxDynamicSharedMemorySize, GEMM_DSM);
    cudaFuncSetAttribute(gemm_mma<false, true,  false>, cudaFuncAttributeMaxDynamicSharedMemorySize, GEMM_DSM);
    cudaFuncSetAttribute(gemm_mma<true,  false, true >, cudaFuncAttributeMaxDynamicSharedMemorySize, GEMM_DSM);
    cudaFuncSetAttribute(attn_kernel, cudaFuncAttributeMaxDynamicSharedMemorySize, ATT_DSM);

    // 1. merged weight cast + ln1
    cast_ln1_kernel<<<3072 + MROWS, 256>>>(w_qkv, w_out, w1, w2, x, ln1_g, ln1_b);
    // 2. qkv = ln1 @ wqkv + b_qkv -> g_qkvh (fp16)
    gemm_mma<false, false, true><<<dim3(24, 32), 256, GEMM_DSM>>>(
        3072, 1024, 1, 3, b_qkv, nullptr, 0, nullptr, 8);
    // 3. HMMA attention -> g_ctx (fp16)
    attn_kernel<<<dim3(16, 16, 2), 256, ATT_DSM>>>(respos);
    // 4. x1 = x + ctx @ wout + b_out -> g_x1 (fp32)
    gemm_mma<false, true, false><<<dim3(8, 32), 256, GEMM_DSM>>>(
        1024, 1024, 2, 4, b_out, x, 0, nullptr, 2);
    // 5. ln2 -> g_ln
    ln_h_kernel<<<MROWS, 256>>>(nullptr, 2, ln2_g, ln2_b);
    // 6. ffn1 = relu(ln2 @ w1 + b1) -> g_ffn1 (fp16)
    gemm_mma<true, false, true><<<dim3(32, 32), 256, GEMM_DSM>>>(
        4096, 1024, 1, 5, b1, nullptr, 0, nullptr, 7);
    // 7. out = x1 + ffn1 @ w2 + b2 -> d_out (fp32)
    gemm_mma<false, true, false><<<dim3(8, 32), 256, GEMM_DSM>>>(
        1024, 4096, 7, 6, b2, nullptr, 2, out, 0);
}